// round 15
// baseline (speedup 1.0000x reference)
#include <cuda_runtime.h>
#include <cuda_fp16.h>
#include <cstdint>

// =============================================================================
// RAFF_8555574853896 — round 15: deeper stream overlap. split_hi(q) hidden
// under the pre-chain; attn split into attn_score (after qM, DRAM-bound) and
// attn_final (after cls), with cls on the side stream overlapping attn_score.
// Numerics identical to round 14 (rel_err ~4.0e-4).
//
// Algebra:
//   scores = q Mt^T q^T / sqrt(D) + rank-1 bias,  Mt = (Wq^T Wk)^T
//   audio  = (w_a^T q) Cov^T + bcomb,             Cov = out_w Wv
// =============================================================================

namespace raff {

constexpr int B = 2048, S = 32, P = 16, D = 1024, H = 512, F = 512;
constexpr long NQ = (long)B * S * D;

constexpr float SWT = 32.f;
constexpr float SC_QW = 1.f / SWT;
constexpr float SC_WW = 1.f / (SWT * SWT);

// ---------------- static device scratch ----------------
__device__ float g_vq[D], g_vk[D], g_bcomb[D];
__device__ float g_c0;
__device__ float g_MC[2 * D * D];              // [Mt; Cov] fp32
__device__ float g_d[B * S];
__device__ float g_attn[(long)B * S * S];      // softmaxed attention (8 MB)
__device__ float g_y[3L * B * F];
__device__ float g_hbias[3 * F];

__device__ __half g_qM_h[NQ];                  // qM fp16 (128 MB)
__device__ __half g_q_hi[NQ];
__device__ __half g_w1_hi[(long)S * H * D];
__device__ __half g_u_hi[2 * D * D], g_u_lo[2 * D * D];    // [WkT; out_w] x32
__device__ __half g_v_hi[2 * D * D], g_v_lo[2 * D * D];    // [WqT; WvT] x32
__device__ __half g_mc_hi[2 * D * D], g_mc_lo[2 * D * D];  // [Mt; Cov] x32
__device__ __half g_qv_hi[2L * B * D];
__device__ __half g_x_hi[3L * B * D];          // fusion | audio | video
__device__ __half g_hw_hi[3L * F * D], g_hw_lo[3L * F * D];

// ---------------- PTX helpers (base sm_103-legal) ----------------
__device__ __forceinline__ uint32_t smem_u32(const void* p) {
    uint32_t a;
    asm("{ .reg .u64 t; cvta.to.shared.u64 t, %1; cvt.u32.u64 %0, t; }"
        : "=r"(a) : "l"(p));
    return a;
}
#define CP16(dst, src) \
    asm volatile("cp.async.cg.shared.global [%0], [%1], 16;" :: "r"(dst), "l"(src))
#define CP_COMMIT() asm volatile("cp.async.commit_group;" ::: "memory")

__device__ __forceinline__ void ldsm_x4(uint32_t* r, uint32_t addr) {
    asm volatile("ldmatrix.sync.aligned.m8n8.x4.shared.b16 {%0,%1,%2,%3}, [%4];"
                 : "=r"(r[0]), "=r"(r[1]), "=r"(r[2]), "=r"(r[3]) : "r"(addr));
}
__device__ __forceinline__ void ldsm_x2(uint32_t* r, uint32_t addr) {
    asm volatile("ldmatrix.sync.aligned.m8n8.x2.shared.b16 {%0,%1}, [%2];"
                 : "=r"(r[0]), "=r"(r[1]) : "r"(addr));
}
__device__ __forceinline__ void mma_f16(float* c, const uint32_t* a, const uint32_t* b) {
    asm volatile(
        "mma.sync.aligned.m16n8k16.row.col.f32.f16.f16.f32 "
        "{%0,%1,%2,%3}, {%4,%5,%6,%7}, {%8,%9}, {%0,%1,%2,%3};"
        : "+f"(c[0]), "+f"(c[1]), "+f"(c[2]), "+f"(c[3])
        : "r"(a[0]), "r"(a[1]), "r"(a[2]), "r"(a[3]), "r"(b[0]), "r"(b[1]));
}

__device__ __forceinline__ uint32_t swz(int r, int c) {
    return (uint32_t)((r * 4 + (c ^ ((r >> 1) & 3))) * 16);
}

__device__ __forceinline__ void hsplit(float x, float s, __half& hi, __half& lo) {
    const float xs = x * s;
    hi = __float2half_rn(xs);
    lo = __float2half_rn(xs - __half2float(hi));
}

// =============================================================================
// fp16 split GEMM. Block 128x128, 8 warps (2m x 4n), warp 64x32, 3 stages.
// TERMS==1: K-chunk 64 + x4 B loads.  TERMS>=2: K-chunk 32.
// =============================================================================
constexpr int STAGE = 32768;
constexpr int NSTG = 3;
constexpr int GEMM_SMEM = NSTG * STAGE;

template <int TERMS, bool BIAS, bool CLSD, bool HOUT>
__global__ void __launch_bounds__(256, 2) bsgemm(
    const __half* __restrict__ Ahi, const __half* __restrict__ Alo,
    long lda, long aOffZ,
    const __half* __restrict__ Bhi, const __half* __restrict__ Blo,
    long bOffZ,
    float* __restrict__ C, int ldc, long cOffZ,
    const float* __restrict__ bias, long biasOffZ,
    const float* __restrict__ w2p, float scaleC)
{
    extern __shared__ char dsm[];
    const uint32_t base = smem_u32(dsm);

    const int tid = threadIdx.x, lane = tid & 31, w = tid >> 5;
    const int wm = w & 1, wn = w >> 1;
    const int z = blockIdx.z;
    const long m0 = (long)blockIdx.y * 128;
    const long n0 = (long)blockIdx.x * 128;
    Ahi += z * aOffZ;
    if (TERMS >= 3) Alo += z * aOffZ;
    Bhi += z * bOffZ;
    if (TERMS >= 2) Blo += z * bOffZ;
    C += z * cOffZ;
    if (BIAS || CLSD) bias += z * biasOffZ;

    float acc[4][4][4];
#pragma unroll
    for (int i = 0; i < 4; i++)
#pragma unroll
        for (int j = 0; j < 4; j++)
#pragma unroll
            for (int k = 0; k < 4; k++) acc[i][j][k] = 0.f;

    auto loadChunk = [&](int s, int kc) {
        const long k0 = (long)kc * 32;
        const uint32_t ah = base + s * STAGE;
        const uint32_t al = ah + 8192;
        const uint32_t bh = ah + 16384;
        const uint32_t bl = ah + 24576;
#pragma unroll
        for (int i = 0; i < 2; i++) {
            const int idx = tid + 256 * i;
            const int r = idx >> 2, c = idx & 3;
            const uint32_t dst = swz(r, c);
            const long offA = (m0 + r) * lda + k0 + c * 8;
            CP16(ah + dst, Ahi + offA);
            if (TERMS >= 3) CP16(al + dst, Alo + offA);
            const long offB = (n0 + r) * 1024 + k0 + c * 8;
            CP16(bh + dst, Bhi + offB);
            if (TERMS >= 2) CP16(bl + dst, Blo + offB);
        }
        CP_COMMIT();
    };

    auto computeChunk = [&](int s) {
        const uint32_t ah = base + s * STAGE;
        const uint32_t al = ah + 8192;
        const uint32_t bh = ah + 16384;
        const uint32_t bl = ah + 24576;
#pragma unroll
        for (int ks = 0; ks < 2; ks++) {
            uint32_t afh[4][4], afl[4][4], bf[4][2];
            const int arow = wm * 64 + (lane & 15);
            const int akc = ks * 2 + (lane >> 4);
#pragma unroll
            for (int i = 0; i < 4; i++) {
                const uint32_t off = swz(arow + i * 16, akc);
                ldsm_x4(afh[i], ah + off);
                if (TERMS >= 3) ldsm_x4(afl[i], al + off);
            }
            const int brow = wn * 32 + (lane & 7);
            const int bkc = ks * 2 + ((lane >> 3) & 1);
#pragma unroll
            for (int j = 0; j < 4; j++)
                ldsm_x2(bf[j], bh + swz(brow + j * 8, bkc));
#pragma unroll
            for (int i = 0; i < 4; i++)
#pragma unroll
                for (int j = 0; j < 4; j++) mma_f16(acc[i][j], afh[i], bf[j]);
            if (TERMS >= 3) {
#pragma unroll
                for (int i = 0; i < 4; i++)
#pragma unroll
                    for (int j = 0; j < 4; j++) mma_f16(acc[i][j], afl[i], bf[j]);
            }
            if (TERMS >= 2) {
#pragma unroll
                for (int j = 0; j < 4; j++)
                    ldsm_x2(bf[j], bl + swz(brow + j * 8, bkc));
#pragma unroll
                for (int i = 0; i < 4; i++)
#pragma unroll
                    for (int j = 0; j < 4; j++) mma_f16(acc[i][j], afh[i], bf[j]);
            }
        }
    };

    auto load64 = [&](int s, int kc) {
        const long k0 = (long)kc * 64;
        const uint32_t ah = base + s * STAGE;
        const uint32_t bh = ah + 16384;
#pragma unroll
        for (int i = 0; i < 4; i++) {
            const int u = tid + 256 * i;
            const int r = u >> 3, uu = u & 7;
            const int sub = uu >> 2, c = uu & 3;
            const uint32_t dst = sub * 8192 + swz(r, c);
            CP16(ah + dst, Ahi + (m0 + r) * lda + k0 + uu * 8);
            CP16(bh + dst, Bhi + (n0 + r) * 1024 + k0 + uu * 8);
        }
        CP_COMMIT();
    };

    auto compute64 = [&](int s) {
        const uint32_t ah = base + s * STAGE;
        const uint32_t bh = ah + 16384;
#pragma unroll
        for (int sub = 0; sub < 2; sub++) {
            const uint32_t ac = ah + sub * 8192;
            const uint32_t bc = bh + sub * 8192;
#pragma unroll
            for (int ks = 0; ks < 2; ks++) {
                uint32_t af[4][4], bq[2][4];
                const int arow = wm * 64 + (lane & 15);
                const int akc = ks * 2 + (lane >> 4);
#pragma unroll
                for (int i = 0; i < 4; i++)
                    ldsm_x4(af[i], ac + swz(arow + i * 16, akc));
                const int bnr = wn * 32 + ((lane >> 4) & 1) * 8 + (lane & 7);
                const int bkc = ks * 2 + ((lane >> 3) & 1);
#pragma unroll
                for (int jj = 0; jj < 2; jj++)
                    ldsm_x4(bq[jj], bc + swz(bnr + jj * 16, bkc));
#pragma unroll
                for (int i = 0; i < 4; i++)
#pragma unroll
                    for (int j = 0; j < 4; j++)
                        mma_f16(acc[i][j], af[i], &bq[j >> 1][(j & 1) * 2]);
            }
        }
    };

    if (TERMS == 1) {
        load64(0, 0);
        load64(1, 1);
        for (int ch = 0; ch < 16; ch++) {
            asm volatile("cp.async.wait_group 1;" ::: "memory");
            __syncthreads();
            if (ch + 2 < 16) load64((ch + 2) % 3, ch + 2);
            else CP_COMMIT();
            compute64(ch % 3);
        }
    } else {
        loadChunk(0, 0);
        loadChunk(1, 1);
        for (int ch = 0; ch < 32; ch++) {
            asm volatile("cp.async.wait_group 1;" ::: "memory");
            __syncthreads();
            if (ch + 2 < 32) loadChunk((ch + 2) % 3, ch + 2);
            else CP_COMMIT();
            computeChunk(ch % 3);
        }
    }

    const int gr = lane >> 2, qd = lane & 3;

    if (CLSD) {
        float p[4][2];
#pragma unroll
        for (int i = 0; i < 4; i++) { p[i][0] = 0.f; p[i][1] = 0.f; }
        const float* w2 = w2p + (long)z * H;
#pragma unroll
        for (int j = 0; j < 4; j++) {
            const long c = n0 + wn * 32 + j * 8 + qd * 2;
            const float2 w2v = *(const float2*)&w2[c];
            const float2 bv = *(const float2*)&bias[c];
#pragma unroll
            for (int i = 0; i < 4; i++) {
                const float h0 = fmaxf(acc[i][j][0] * scaleC + bv.x, 0.f);
                const float h1 = fmaxf(acc[i][j][1] * scaleC + bv.y, 0.f);
                p[i][0] += h0 * w2v.x + h1 * w2v.y;
                const float h2 = fmaxf(acc[i][j][2] * scaleC + bv.x, 0.f);
                const float h3 = fmaxf(acc[i][j][3] * scaleC + bv.y, 0.f);
                p[i][1] += h2 * w2v.x + h3 * w2v.y;
            }
        }
#pragma unroll
        for (int i = 0; i < 4; i++) {
            p[i][0] += __shfl_xor_sync(~0u, p[i][0], 1);
            p[i][0] += __shfl_xor_sync(~0u, p[i][0], 2);
            p[i][1] += __shfl_xor_sync(~0u, p[i][1], 1);
            p[i][1] += __shfl_xor_sync(~0u, p[i][1], 2);
            if (qd == 0) {
                const long r = m0 + wm * 64 + i * 16 + gr;
                atomicAdd(&C[r * S + z], p[i][0]);
                atomicAdd(&C[(r + 8) * S + z], p[i][1]);
            }
        }
    } else {
#pragma unroll
        for (int j = 0; j < 4; j++) {
            const long c = n0 + wn * 32 + j * 8 + qd * 2;
            float2 bv = make_float2(0.f, 0.f);
            if (BIAS) bv = *(const float2*)&bias[c];
#pragma unroll
            for (int i = 0; i < 4; i++) {
                const long r0 = m0 + wm * 64 + i * 16 + gr;
                float2 v0 = make_float2(acc[i][j][0] * scaleC + bv.x,
                                        acc[i][j][1] * scaleC + bv.y);
                float2 v1 = make_float2(acc[i][j][2] * scaleC + bv.x,
                                        acc[i][j][3] * scaleC + bv.y);
                if (HOUT) {
                    __half* Ch = (__half*)C;
                    *(__half2*)&Ch[r0 * ldc + c] = __floats2half2_rn(v0.x, v0.y);
                    *(__half2*)&Ch[(r0 + 8) * ldc + c] = __floats2half2_rn(v1.x, v1.y);
                } else {
                    *(float2*)&C[r0 * ldc + c] = v0;
                    *(float2*)&C[(r0 + 8) * ldc + c] = v1;
                }
            }
        }
    }
}

// =============================================================================
// conversion kernels
// =============================================================================
__global__ void split4(const float* __restrict__ src, __half* __restrict__ hi,
                       __half* __restrict__ lo, long n4, float s)
{
    const long i = (long)blockIdx.x * 256 + threadIdx.x;
    if (i >= n4) return;
    float4 v = ((const float4*)src)[i];
    __half h0, h1, h2, h3, l0, l1, l2, l3;
    hsplit(v.x, s, h0, l0);
    hsplit(v.y, s, h1, l1);
    hsplit(v.z, s, h2, l2);
    hsplit(v.w, s, h3, l3);
    __half2 a, b;
    a.x = h0; a.y = h1; b.x = h2; b.y = h3;
    ((__half2*)hi)[2 * i] = a; ((__half2*)hi)[2 * i + 1] = b;
    a.x = l0; a.y = l1; b.x = l2; b.y = l3;
    ((__half2*)lo)[2 * i] = a; ((__half2*)lo)[2 * i + 1] = b;
}

__global__ void split_hi(const float* __restrict__ src, __half* __restrict__ hi,
                         long n4)
{
    const long i = (long)blockIdx.x * 256 + threadIdx.x;
    if (i >= n4) return;
    float4 v = ((const float4*)src)[i];
    __half2 a, b;
    a.x = __float2half_rn(v.x); a.y = __float2half_rn(v.y);
    b.x = __float2half_rn(v.z); b.y = __float2half_rn(v.w);
    ((__half2*)hi)[2 * i] = a; ((__half2*)hi)[2 * i + 1] = b;
}

__global__ void tsplit(const float* __restrict__ src, __half* __restrict__ hi,
                       __half* __restrict__ lo)
{
    __shared__ float t[32][33];
    const int bx = blockIdx.x * 32, by = blockIdx.y * 32;
    const int tx = threadIdx.x;
    for (int j = threadIdx.y; j < 32; j += 8)
        t[j][tx] = src[(long)(by + j) * 1024 + bx + tx];
    __syncthreads();
    for (int j = threadIdx.y; j < 32; j += 8) {
        const long o = (long)(bx + j) * 1024 + by + tx;
        __half h, l;
        hsplit(t[tx][j], SWT, h, l);
        hi[o] = h; lo[o] = l;
    }
}

__global__ void fuse_half()
{
    const long i = (long)blockIdx.x * 256 + threadIdx.x;
    const __half2* a = (const __half2*)(g_x_hi + (long)B * D);
    const __half2* v = (const __half2*)(g_x_hi + 2L * B * D);
    __half2* f = (__half2*)g_x_hi;
#pragma unroll
    for (int j = 0; j < 4; j++) {
        float2 xf = __half22float2(a[4 * i + j]);
        float2 yf = __half22float2(v[4 * i + j]);
        f[4 * i + j] = __floats2half2_rn(0.5f * (xf.x + yf.x), 0.5f * (xf.y + yf.y));
    }
}

__global__ void misc_init(const float* __restrict__ b0, const float* __restrict__ b1,
                          const float* __restrict__ b2)
{
    const int blk = blockIdx.x;
    if (blk < 256) { g_d[blk * 256 + threadIdx.x] = 0.f; return; }
    const int i = (blk - 256) * 256 + threadIdx.x;
    if (i < 3 * F) {
        const int hh = i >> 9, j = i & 511;
        g_hbias[i] = hh == 0 ? b0[j] : (hh == 1 ? b1[j] : b2[j]);
    }
}

// =============================================================================
// bias-derived vectors
// =============================================================================
__global__ void __launch_bounds__(256) vec_pre(
    const float* __restrict__ in_proj_w, const float* __restrict__ in_proj_b,
    const float* __restrict__ out_w, const float* __restrict__ out_b)
{
    const float* wq = in_proj_w;
    const float* wk = in_proj_w + (long)D * D;
    const float* bq = in_proj_b;
    const float* bk = in_proj_b + D;
    const float* bv = in_proj_b + 2 * D;
    __shared__ float rs[3][8];
    const int t = threadIdx.x, w = t >> 5, lane = t & 31;
    const int i = blockIdx.x;
    float v0 = 0.f, v1 = 0.f, v2 = 0.f;
    if (i < D) {
        for (int e = t; e < D; e += 256) {
            v0 = fmaf(bq[e], wk[(long)e * D + i], v0);
            v1 = fmaf(bk[e], wq[(long)e * D + i], v1);
            v2 = fmaf(out_w[(long)i * D + e], bv[e], v2);
        }
    } else {
        for (int e = t; e < D; e += 256) v0 = fmaf(bq[e], bk[e], v0);
    }
#pragma unroll
    for (int o = 16; o > 0; o >>= 1) {
        v0 += __shfl_xor_sync(~0u, v0, o);
        v1 += __shfl_xor_sync(~0u, v1, o);
        v2 += __shfl_xor_sync(~0u, v2, o);
    }
    if (lane == 0) { rs[0][w] = v0; rs[1][w] = v1; rs[2][w] = v2; }
    __syncthreads();
    if (t == 0) {
        float s0 = 0.f, s1 = 0.f, s2 = 0.f;
#pragma unroll
        for (int j = 0; j < 8; j++) { s0 += rs[0][j]; s1 += rs[1][j]; s2 += rs[2][j]; }
        if (i < D) { g_vq[i] = s0; g_vk[i] = s1; g_bcomb[i] = s2 + out_b[i]; }
        else g_c0 = s0;
    }
}

// =============================================================================
// attn_score: HMMA scores + row softmax -> g_attn. Needs qM + q only.
// =============================================================================
constexpr int ATTNS_SMEM = 65536 + 65536 + 8 * 32 * 33 * 4;

__global__ void __launch_bounds__(256) attn_score()
{
    extern __shared__ char dsm[];
    const uint32_t sbase = smem_u32(dsm);
    const uint32_t QOFF = 0, QMOFF = 65536, POFF = 131072;
    float* part = (float*)(dsm + POFF);

    __shared__ float sc[32][33];
    __shared__ float vks[1024];
    __shared__ float rk[32];

    const int b = blockIdx.x;
    const int tid = threadIdx.x, w = tid >> 5, lane = tid & 31;
    const __half* qbh = g_q_hi + (long)b * S * D;
    const __half* qmbh = g_qM_h + (long)b * S * D;

#pragma unroll
    for (int i = 0; i < 16; i++) {
        const int u = tid + 256 * i;
        const int r = (u >> 7);
        const int uu = u & 127;
        const int kc = uu >> 2, c = uu & 3;
        const long src = (long)r * D + uu * 8;
        CP16(sbase + QOFF + kc * 2048 + swz(r, c), qbh + src);
        CP16(sbase + QMOFF + kc * 2048 + swz(r, c), qmbh + src);
    }
    CP_COMMIT();
#pragma unroll
    for (int i = 0; i < 4; i++) vks[tid + 256 * i] = g_vk[tid + 256 * i];
    asm volatile("cp.async.wait_group 0;" ::: "memory");
    __syncthreads();

    {
        float acc[2][4][4];
#pragma unroll
        for (int i = 0; i < 2; i++)
#pragma unroll
            for (int j = 0; j < 4; j++)
#pragma unroll
                for (int k = 0; k < 4; k++) acc[i][j][k] = 0.f;
#pragma unroll
        for (int cc = 0; cc < 4; cc++) {
            const uint32_t qc = sbase + QOFF + (4 * w + cc) * 2048;
            const uint32_t qmc = sbase + QMOFF + (4 * w + cc) * 2048;
#pragma unroll
            for (int ks = 0; ks < 2; ks++) {
                uint32_t af[2][4], bf[4][2];
                const int arow = lane & 15;
                const int akc = ks * 2 + (lane >> 4);
#pragma unroll
                for (int i = 0; i < 2; i++)
                    ldsm_x4(af[i], qmc + swz(i * 16 + arow, akc));
                const int brow = lane & 7;
                const int bkc = ks * 2 + ((lane >> 3) & 1);
#pragma unroll
                for (int j = 0; j < 4; j++)
                    ldsm_x2(bf[j], qc + swz(j * 8 + brow, bkc));
#pragma unroll
                for (int i = 0; i < 2; i++)
#pragma unroll
                    for (int j = 0; j < 4; j++) mma_f16(acc[i][j], af[i], bf[j]);
            }
        }
        float* pw = part + w * 1056;
        const int gr = lane >> 2, qd = lane & 3;
#pragma unroll
        for (int i = 0; i < 2; i++)
#pragma unroll
            for (int j = 0; j < 4; j++) {
                const int r = i * 16 + gr, c = j * 8 + qd * 2;
                pw[r * 33 + c] = acc[i][j][0];
                pw[r * 33 + c + 1] = acc[i][j][1];
                pw[(r + 8) * 33 + c] = acc[i][j][2];
                pw[(r + 8) * 33 + c + 1] = acc[i][j][3];
            }
    }
    __syncthreads();

#pragma unroll
    for (int i = 0; i < 4; i++) {
        const int e = tid + 256 * i;
        const int r = e >> 5, c = e & 31;
        float s = 0.f;
#pragma unroll
        for (int ww = 0; ww < 8; ww++) s += part[ww * 1056 + r * 33 + c];
        sc[r][c] = s;
    }
    {
        const int row = tid >> 3, seg = tid & 7;
        float r2 = 0.f;
        for (int j = 0; j < 128; j++) {
            const int k = seg * 128 + j;
            const uint32_t off = QOFF + (k >> 5) * 2048 + swz(row, (k >> 3) & 3) + (k & 7) * 2;
            r2 = fmaf(__half2float(*(const __half*)(dsm + off)), vks[k], r2);
        }
        r2 += __shfl_xor_sync(~0u, r2, 1);
        r2 += __shfl_xor_sync(~0u, r2, 2);
        r2 += __shfl_xor_sync(~0u, r2, 4);
        if (seg == 0) rk[row] = r2;
    }
    __syncthreads();

    const float inv_sqrtD = 0.03125f;
    for (int rr = w * 4; rr < w * 4 + 4; rr++) {
        float v = (sc[rr][lane] + rk[rr] + g_c0) * inv_sqrtD;
        float mx = v;
#pragma unroll
        for (int o = 16; o > 0; o >>= 1) mx = fmaxf(mx, __shfl_xor_sync(~0u, mx, o));
        float e = __expf(v - mx);
        float sum = e;
#pragma unroll
        for (int o = 16; o > 0; o >>= 1) sum += __shfl_xor_sync(~0u, sum, o);
        g_attn[(long)b * 1024 + rr * 32 + lane] = e / sum;
    }
}

// =============================================================================
// attn_final: d softmaxes + weighted q sums. Needs g_d + g_attn + q tile.
// =============================================================================
constexpr int ATTNF_SMEM = 65536;

__global__ void __launch_bounds__(256) attn_final(
    const float* __restrict__ cls_b2, float* __restrict__ out)
{
    extern __shared__ char dsm[];
    const uint32_t sbase = smem_u32(dsm);

    __shared__ float sc[32][33];
    __shared__ float dd[32], wa[32], wvv[32], da[16], dv[16];

    const int b = blockIdx.x;
    const int tid = threadIdx.x;
    const __half* qbh = g_q_hi + (long)b * S * D;

#pragma unroll
    for (int i = 0; i < 16; i++) {
        const int u = tid + 256 * i;
        const int r = (u >> 7);
        const int uu = u & 127;
        const int kc = uu >> 2, c = uu & 3;
        CP16(sbase + kc * 2048 + swz(r, c), qbh + (long)r * D + uu * 8);
    }
    CP_COMMIT();
#pragma unroll
    for (int i = 0; i < 4; i++) {
        const int e = tid + 256 * i;
        sc[e >> 5][e & 31] = g_attn[(long)b * 1024 + e];
    }
    if (tid < 32) dd[tid] = fmaxf(g_d[b * S + tid] + cls_b2[tid], 0.f);
    __syncthreads();

    if (tid < 32) {
        const bool isA = tid < 16;
        const int i = tid & 15;
        float v = dd[tid];
        float mx = v;
#pragma unroll
        for (int o = 8; o > 0; o >>= 1) mx = fmaxf(mx, __shfl_xor_sync(~0u, mx, o));
        float e = __expf(v - mx);
        float sum = e;
#pragma unroll
        for (int o = 8; o > 0; o >>= 1) sum += __shfl_xor_sync(~0u, sum, o);
        const float p = e / sum;
        if (isA) da[i] = p; else dv[i] = p;
        const long bse = 3L * B * F;
        if (isA) out[bse + (long)b * P + i] = p;
        else     out[bse + (long)B * P + (long)b * P + i] = p;
    }
    __syncthreads();

    if (tid < 32) {
        float a = 0.f, v2 = 0.f;
#pragma unroll
        for (int ss = 0; ss < 16; ss++) a = fmaf(da[ss], sc[ss][tid], a);
#pragma unroll
        for (int ss = 0; ss < 16; ss++) v2 = fmaf(dv[ss], sc[16 + ss][tid], v2);
        wa[tid] = a;
        wvv[tid] = v2;
    }
    asm volatile("cp.async.wait_group 0;" ::: "memory");
    __syncthreads();

#pragma unroll
    for (int i = 0; i < 4; i++) {
        const int col = tid + 256 * i;
        const uint32_t cb = (col >> 5) * 2048;
        const int cc4 = (col >> 3) & 3;
        const int co = (col & 7) * 2;
        float a = 0.f, v2 = 0.f;
#pragma unroll
        for (int t = 0; t < 32; t++) {
            const float x = __half2float(*(const __half*)(dsm + cb + swz(t, cc4) + co));
            a = fmaf(wa[t], x, a);
            v2 = fmaf(wvv[t], x, v2);
        }
        const long ia = (long)b * D + col;
        g_qv_hi[ia] = __float2half_rn(a);
        g_qv_hi[(long)B * D + ia] = __float2half_rn(v2);
    }
}

__global__ void __launch_bounds__(128) ln_relu(
    const float* __restrict__ gm0, const float* __restrict__ be0,
    const float* __restrict__ gm1, const float* __restrict__ be1,
    const float* __restrict__ gm2, const float* __restrict__ be2,
    float* __restrict__ out)
{
    const int head = blockIdx.y, b = blockIdx.x, tid = threadIdx.x;
    const float* gm = head == 0 ? gm0 : (head == 1 ? gm1 : gm2);
    const float* be = head == 0 ? be0 : (head == 1 ? be1 : be2);
    const float* y = g_y + ((long)head * B + b) * F;

    float4 v = *(const float4*)&y[tid * 4];
    float s = v.x + v.y + v.z + v.w;
    float sq = v.x * v.x + v.y * v.y + v.z * v.z + v.w * v.w;
#pragma unroll
    for (int o = 16; o > 0; o >>= 1) {
        s += __shfl_xor_sync(~0u, s, o);
        sq += __shfl_xor_sync(~0u, sq, o);
    }
    __shared__ float ss[4], ssq[4];
    const int w = tid >> 5;
    if ((tid & 31) == 0) { ss[w] = s; ssq[w] = sq; }
    __syncthreads();
    s = ss[0] + ss[1] + ss[2] + ss[3];
    sq = ssq[0] + ssq[1] + ssq[2] + ssq[3];
    const float mean = s * (1.f / F);
    const float var = sq * (1.f / F) - mean * mean;
    const float rstd = rsqrtf(var + 1e-5f);

    float4 g4 = *(const float4*)&gm[tid * 4];
    float4 b4 = *(const float4*)&be[tid * 4];
    float4 o4;
    o4.x = fmaxf((v.x - mean) * rstd * g4.x + b4.x, 0.f);
    o4.y = fmaxf((v.y - mean) * rstd * g4.y + b4.y, 0.f);
    o4.z = fmaxf((v.z - mean) * rstd * g4.z + b4.z, 0.f);
    o4.w = fmaxf((v.w - mean) * rstd * g4.w + b4.w, 0.f);
    *(float4*)&out[((long)head * B + b) * F + tid * 4] = o4;
}

}  // namespace raff

// =============================================================================
// Launch
// =============================================================================
extern "C" void kernel_launch(void* const* d_in, const int* in_sizes, int n_in,
                              void* d_out, int out_size)
{
    using namespace raff;
    (void)in_sizes; (void)n_in; (void)out_size;

    const float* q         = (const float*)d_in[0];
    const float* in_proj_w = (const float*)d_in[1];
    const float* in_proj_b = (const float*)d_in[2];
    const float* out_w     = (const float*)d_in[3];
    const float* out_b     = (const float*)d_in[4];
    const float* cls_w1    = (const float*)d_in[5];
    const float* cls_b1    = (const float*)d_in[6];
    const float* cls_w2    = (const float*)d_in[7];
    const float* cls_b2    = (const float*)d_in[8];
    const float* fus_w     = (const float*)d_in[9];
    const float* fus_b     = (const float*)d_in[10];
    const float* fus_g     = (const float*)d_in[11];
    const float* fus_be    = (const float*)d_in[12];
    const float* pa_w      = (const float*)d_in[13];
    const float* pa_b      = (const float*)d_in[14];
    const float* pa_g      = (const float*)d_in[15];
    const float* pa_be     = (const float*)d_in[16];
    const float* pv_w      = (const float*)d_in[17];
    const float* pv_b      = (const float*)d_in[18];
    const float* pv_g      = (const float*)d_in[19];
    const float* pv_be     = (const float*)d_in[20];
    float* out = (float*)d_out;

    float *pMC, *pd, *py, *pvq, *pbcomb, *phb;
    __half *pqMh, *qhi, *w1hi, *uhi, *ulo, *vhi, *vlo,
        *mchi, *mclo, *qvhi, *xhi, *hwhi, *hwlo;
    cudaGetSymbolAddress((void**)&pMC, g_MC);
    cudaGetSymbolAddress((void**)&pqMh, g_qM_h);
    cudaGetSymbolAddress((void**)&pd, g_d);
    cudaGetSymbolAddress((void**)&py, g_y);
    cudaGetSymbolAddress((void**)&pvq, g_vq);
    cudaGetSymbolAddress((void**)&pbcomb, g_bcomb);
    cudaGetSymbolAddress((void**)&phb, g_hbias);
    cudaGetSymbolAddress((void**)&qhi, g_q_hi);
    cudaGetSymbolAddress((void**)&w1hi, g_w1_hi);
    cudaGetSymbolAddress((void**)&uhi, g_u_hi);
    cudaGetSymbolAddress((void**)&ulo, g_u_lo);
    cudaGetSymbolAddress((void**)&vhi, g_v_hi);
    cudaGetSymbolAddress((void**)&vlo, g_v_lo);
    cudaGetSymbolAddress((void**)&mchi, g_mc_hi);
    cudaGetSymbolAddress((void**)&mclo, g_mc_lo);
    cudaGetSymbolAddress((void**)&qvhi, g_qv_hi);
    cudaGetSymbolAddress((void**)&xhi, g_x_hi);
    cudaGetSymbolAddress((void**)&hwhi, g_hw_hi);
    cudaGetSymbolAddress((void**)&hwlo, g_hw_lo);

    cudaFuncSetAttribute((const void*)bsgemm<3, false, false, false>,
                         cudaFuncAttributeMaxDynamicSharedMemorySize, GEMM_SMEM);
    cudaFuncSetAttribute((const void*)bsgemm<2, true, false, true>,
                         cudaFuncAttributeMaxDynamicSharedMemorySize, GEMM_SMEM);
    cudaFuncSetAttribute((const void*)bsgemm<2, true, false, false>,
                         cudaFuncAttributeMaxDynamicSharedMemorySize, GEMM_SMEM);
    cudaFuncSetAttribute((const void*)bsgemm<1, true, false, true>,
                         cudaFuncAttributeMaxDynamicSharedMemorySize, GEMM_SMEM);
    cudaFuncSetAttribute((const void*)bsgemm<1, false, true, false>,
                         cudaFuncAttributeMaxDynamicSharedMemorySize, GEMM_SMEM);
    cudaFuncSetAttribute((const void*)attn_score,
                         cudaFuncAttributeMaxDynamicSharedMemorySize, ATTNS_SMEM);
    cudaFuncSetAttribute((const void*)attn_final,
                         cudaFuncAttributeMaxDynamicSharedMemorySize, ATTNF_SMEM);

    static cudaStream_t s1 = nullptr;
    static cudaEvent_t ef = nullptr, eq = nullptr, eqm = nullptr, ecls = nullptr;
    if (!s1) {
        cudaStreamCreateWithFlags(&s1, cudaStreamNonBlocking);
        cudaEventCreateWithFlags(&ef, cudaEventDisableTiming);
        cudaEventCreateWithFlags(&eq, cudaEventDisableTiming);
        cudaEventCreateWithFlags(&eqm, cudaEventDisableTiming);
        cudaEventCreateWithFlags(&ecls, cudaEventDisableTiming);
    }

    // ---- fork side stream immediately ----
    cudaEventRecord(ef, 0);
    cudaStreamWaitEvent(s1, ef, 0);

    // side stream: q conversion first (critical for qM), then weight conversions
    split_hi<<<(int)(NQ / 4 / 256), 256, 0, s1>>>(q, qhi, NQ / 4);
    cudaEventRecord(eq, s1);
    split_hi<<<(int)((long)S * H * D / 4 / 256), 256, 0, s1>>>(
        cls_w1, w1hi, (long)S * H * D / 4);
    split4<<<F * D / 4 / 256, 256, 0, s1>>>(fus_w, hwhi, hwlo, (long)F * D / 4, SWT);
    split4<<<F * D / 4 / 256, 256, 0, s1>>>(pa_w, hwhi + (long)F * D,
                                            hwlo + (long)F * D, (long)F * D / 4, SWT);
    split4<<<F * D / 4 / 256, 256, 0, s1>>>(pv_w, hwhi + 2L * F * D,
                                            hwlo + 2L * F * D, (long)F * D / 4, SWT);

    // main stream: pre-chain (overlaps split_hi(q))
    vec_pre<<<D + 1, 256>>>(in_proj_w, in_proj_b, out_w, out_b);
    misc_init<<<262, 256>>>(fus_b, pa_b, pv_b);
    split4<<<D * D / 4 / 256, 256>>>(out_w, uhi + (long)D * D, ulo + (long)D * D,
                                     D * D / 4, SWT);
    tsplit<<<dim3(32, 32), dim3(32, 8)>>>(in_proj_w + (long)D * D, uhi, ulo);    // WkT
    tsplit<<<dim3(32, 32), dim3(32, 8)>>>(in_proj_w, vhi, vlo);                  // WqT
    tsplit<<<dim3(32, 32), dim3(32, 8)>>>(in_proj_w + 2L * D * D,
                                          vhi + (long)D * D, vlo + (long)D * D); // WvT
    bsgemm<3, false, false, false><<<dim3(8, 8, 2), 256, GEMM_SMEM>>>(
        uhi, ulo, D, (long)D * D, vhi, vlo, (long)D * D,
        pMC, D, (long)D * D, nullptr, 0L, nullptr, SC_WW);
    split4<<<2 * D * D / 4 / 256, 256>>>(pMC, mchi, mclo, 2 * D * D / 4, SWT);

    // qM needs qhi (side stream)
    cudaStreamWaitEvent(0, eq, 0);
    bsgemm<1, true, false, true><<<dim3(8, 512), 256, GEMM_SMEM>>>(
        qhi, nullptr, (long)D, 0L, mchi, nullptr, 0L, (float*)pqMh, D, 0L,
        pvq, 0L, nullptr, SC_QW);
    cudaEventRecord(eqm, 0);

    // side stream: cls after qM finishes (tensor pipe free), overlaps attn_score
    cudaStreamWaitEvent(s1, eqm, 0);
    bsgemm<1, false, true, false><<<dim3(4, 16, 32), 256, GEMM_SMEM, s1>>>(
        qhi, nullptr, (long)S * D, (long)D, w1hi, nullptr, (long)H * D,
        pd, S, 0L, cls_b1, (long)H, cls_w2, 1.f);
    cudaEventRecord(ecls, s1);

    // main: attn_score (needs only qM + qhi) overlaps cls
    attn_score<<<B, 256, ATTNS_SMEM>>>();

    // join: attn_final needs d (cls)
    cudaStreamWaitEvent(0, ecls, 0);
    attn_final<<<B, 256, ATTNF_SMEM>>>(cls_b2, out);

    // [audio; video] = qv * Cov^T + bcomb  (2-term, fp16 out)
    bsgemm<2, true, false, true><<<dim3(8, 32), 256, GEMM_SMEM>>>(
        qvhi, nullptr, (long)D, 0L, mchi + (long)D * D, mclo + (long)D * D, 0L,
        (float*)(xhi + (long)B * D), D, 0L, pbcomb, 0L, nullptr, SC_QW);

    fuse_half<<<(int)((long)B * D / 8 / 256), 256>>>();

    // heads (hw conversions ordered via ecls wait: s1 work precedes cls)
    bsgemm<2, true, false, false><<<dim3(4, 16, 3), 256, GEMM_SMEM>>>(
        xhi, nullptr, (long)D, (long)B * D, hwhi, hwlo, (long)F * D,
        py, F, (long)B * F, phb, (long)F, nullptr, SC_QW);

    ln_relu<<<dim3(B, 3), 128>>>(fus_g, fus_be, pa_g, pa_be, pv_g, pv_be, out);
}

// round 16
// speedup vs baseline: 1.0103x; 1.0103x over previous
#include <cuda_runtime.h>
#include <cuda_fp16.h>
#include <cstdint>

// =============================================================================
// RAFF_8555574853896 — round 16: revert to round-14 structure (single attn
// kernel); NEW: qM and cls GEMMs run concurrently on two streams (both depend
// only on qhi + their weights), join before attn. Numerics identical to R14.
//
// Algebra:
//   scores = q Mt^T q^T / sqrt(D) + rank-1 bias,  Mt = (Wq^T Wk)^T
//   audio  = (w_a^T q) Cov^T + bcomb,             Cov = out_w Wv
// =============================================================================

namespace raff {

constexpr int B = 2048, S = 32, P = 16, D = 1024, H = 512, F = 512;
constexpr long NQ = (long)B * S * D;

constexpr float SWT = 32.f;
constexpr float SC_QW = 1.f / SWT;
constexpr float SC_WW = 1.f / (SWT * SWT);

// ---------------- static device scratch ----------------
__device__ float g_vq[D], g_vk[D], g_bcomb[D];
__device__ float g_c0;
__device__ float g_MC[2 * D * D];              // [Mt; Cov] fp32
__device__ float g_d[B * S];
__device__ float g_y[3L * B * F];
__device__ float g_hbias[3 * F];

__device__ __half g_qM_h[NQ];                  // qM fp16 (128 MB)
__device__ __half g_q_hi[NQ];
__device__ __half g_w1_hi[(long)S * H * D];
__device__ __half g_u_hi[2 * D * D], g_u_lo[2 * D * D];    // [WkT; out_w] x32
__device__ __half g_v_hi[2 * D * D], g_v_lo[2 * D * D];    // [WqT; WvT] x32
__device__ __half g_mc_hi[2 * D * D], g_mc_lo[2 * D * D];  // [Mt; Cov] x32
__device__ __half g_qv_hi[2L * B * D];
__device__ __half g_x_hi[3L * B * D];          // fusion | audio | video
__device__ __half g_hw_hi[3L * F * D], g_hw_lo[3L * F * D];

// ---------------- PTX helpers (base sm_103-legal) ----------------
__device__ __forceinline__ uint32_t smem_u32(const void* p) {
    uint32_t a;
    asm("{ .reg .u64 t; cvta.to.shared.u64 t, %1; cvt.u32.u64 %0, t; }"
        : "=r"(a) : "l"(p));
    return a;
}
#define CP16(dst, src) \
    asm volatile("cp.async.cg.shared.global [%0], [%1], 16;" :: "r"(dst), "l"(src))
#define CP_COMMIT() asm volatile("cp.async.commit_group;" ::: "memory")

__device__ __forceinline__ void ldsm_x4(uint32_t* r, uint32_t addr) {
    asm volatile("ldmatrix.sync.aligned.m8n8.x4.shared.b16 {%0,%1,%2,%3}, [%4];"
                 : "=r"(r[0]), "=r"(r[1]), "=r"(r[2]), "=r"(r[3]) : "r"(addr));
}
__device__ __forceinline__ void ldsm_x2(uint32_t* r, uint32_t addr) {
    asm volatile("ldmatrix.sync.aligned.m8n8.x2.shared.b16 {%0,%1}, [%2];"
                 : "=r"(r[0]), "=r"(r[1]) : "r"(addr));
}
__device__ __forceinline__ void mma_f16(float* c, const uint32_t* a, const uint32_t* b) {
    asm volatile(
        "mma.sync.aligned.m16n8k16.row.col.f32.f16.f16.f32 "
        "{%0,%1,%2,%3}, {%4,%5,%6,%7}, {%8,%9}, {%0,%1,%2,%3};"
        : "+f"(c[0]), "+f"(c[1]), "+f"(c[2]), "+f"(c[3])
        : "r"(a[0]), "r"(a[1]), "r"(a[2]), "r"(a[3]), "r"(b[0]), "r"(b[1]));
}

__device__ __forceinline__ uint32_t swz(int r, int c) {
    return (uint32_t)((r * 4 + (c ^ ((r >> 1) & 3))) * 16);
}

__device__ __forceinline__ void hsplit(float x, float s, __half& hi, __half& lo) {
    const float xs = x * s;
    hi = __float2half_rn(xs);
    lo = __float2half_rn(xs - __half2float(hi));
}

// =============================================================================
// fp16 split GEMM. Block 128x128, 8 warps (2m x 4n), warp 64x32, 3 stages.
// TERMS==1: K-chunk 64 + x4 B loads.  TERMS>=2: K-chunk 32.
// =============================================================================
constexpr int STAGE = 32768;
constexpr int NSTG = 3;
constexpr int GEMM_SMEM = NSTG * STAGE;

template <int TERMS, bool BIAS, bool CLSD, bool HOUT>
__global__ void __launch_bounds__(256, 2) bsgemm(
    const __half* __restrict__ Ahi, const __half* __restrict__ Alo,
    long lda, long aOffZ,
    const __half* __restrict__ Bhi, const __half* __restrict__ Blo,
    long bOffZ,
    float* __restrict__ C, int ldc, long cOffZ,
    const float* __restrict__ bias, long biasOffZ,
    const float* __restrict__ w2p, float scaleC)
{
    extern __shared__ char dsm[];
    const uint32_t base = smem_u32(dsm);

    const int tid = threadIdx.x, lane = tid & 31, w = tid >> 5;
    const int wm = w & 1, wn = w >> 1;
    const int z = blockIdx.z;
    const long m0 = (long)blockIdx.y * 128;
    const long n0 = (long)blockIdx.x * 128;
    Ahi += z * aOffZ;
    if (TERMS >= 3) Alo += z * aOffZ;
    Bhi += z * bOffZ;
    if (TERMS >= 2) Blo += z * bOffZ;
    C += z * cOffZ;
    if (BIAS || CLSD) bias += z * biasOffZ;

    float acc[4][4][4];
#pragma unroll
    for (int i = 0; i < 4; i++)
#pragma unroll
        for (int j = 0; j < 4; j++)
#pragma unroll
            for (int k = 0; k < 4; k++) acc[i][j][k] = 0.f;

    auto loadChunk = [&](int s, int kc) {
        const long k0 = (long)kc * 32;
        const uint32_t ah = base + s * STAGE;
        const uint32_t al = ah + 8192;
        const uint32_t bh = ah + 16384;
        const uint32_t bl = ah + 24576;
#pragma unroll
        for (int i = 0; i < 2; i++) {
            const int idx = tid + 256 * i;
            const int r = idx >> 2, c = idx & 3;
            const uint32_t dst = swz(r, c);
            const long offA = (m0 + r) * lda + k0 + c * 8;
            CP16(ah + dst, Ahi + offA);
            if (TERMS >= 3) CP16(al + dst, Alo + offA);
            const long offB = (n0 + r) * 1024 + k0 + c * 8;
            CP16(bh + dst, Bhi + offB);
            if (TERMS >= 2) CP16(bl + dst, Blo + offB);
        }
        CP_COMMIT();
    };

    auto computeChunk = [&](int s) {
        const uint32_t ah = base + s * STAGE;
        const uint32_t al = ah + 8192;
        const uint32_t bh = ah + 16384;
        const uint32_t bl = ah + 24576;
#pragma unroll
        for (int ks = 0; ks < 2; ks++) {
            uint32_t afh[4][4], afl[4][4], bf[4][2];
            const int arow = wm * 64 + (lane & 15);
            const int akc = ks * 2 + (lane >> 4);
#pragma unroll
            for (int i = 0; i < 4; i++) {
                const uint32_t off = swz(arow + i * 16, akc);
                ldsm_x4(afh[i], ah + off);
                if (TERMS >= 3) ldsm_x4(afl[i], al + off);
            }
            const int brow = wn * 32 + (lane & 7);
            const int bkc = ks * 2 + ((lane >> 3) & 1);
#pragma unroll
            for (int j = 0; j < 4; j++)
                ldsm_x2(bf[j], bh + swz(brow + j * 8, bkc));
#pragma unroll
            for (int i = 0; i < 4; i++)
#pragma unroll
                for (int j = 0; j < 4; j++) mma_f16(acc[i][j], afh[i], bf[j]);
            if (TERMS >= 3) {
#pragma unroll
                for (int i = 0; i < 4; i++)
#pragma unroll
                    for (int j = 0; j < 4; j++) mma_f16(acc[i][j], afl[i], bf[j]);
            }
            if (TERMS >= 2) {
#pragma unroll
                for (int j = 0; j < 4; j++)
                    ldsm_x2(bf[j], bl + swz(brow + j * 8, bkc));
#pragma unroll
                for (int i = 0; i < 4; i++)
#pragma unroll
                    for (int j = 0; j < 4; j++) mma_f16(acc[i][j], afh[i], bf[j]);
            }
        }
    };

    auto load64 = [&](int s, int kc) {
        const long k0 = (long)kc * 64;
        const uint32_t ah = base + s * STAGE;
        const uint32_t bh = ah + 16384;
#pragma unroll
        for (int i = 0; i < 4; i++) {
            const int u = tid + 256 * i;
            const int r = u >> 3, uu = u & 7;
            const int sub = uu >> 2, c = uu & 3;
            const uint32_t dst = sub * 8192 + swz(r, c);
            CP16(ah + dst, Ahi + (m0 + r) * lda + k0 + uu * 8);
            CP16(bh + dst, Bhi + (n0 + r) * 1024 + k0 + uu * 8);
        }
        CP_COMMIT();
    };

    auto compute64 = [&](int s) {
        const uint32_t ah = base + s * STAGE;
        const uint32_t bh = ah + 16384;
#pragma unroll
        for (int sub = 0; sub < 2; sub++) {
            const uint32_t ac = ah + sub * 8192;
            const uint32_t bc = bh + sub * 8192;
#pragma unroll
            for (int ks = 0; ks < 2; ks++) {
                uint32_t af[4][4], bq[2][4];
                const int arow = wm * 64 + (lane & 15);
                const int akc = ks * 2 + (lane >> 4);
#pragma unroll
                for (int i = 0; i < 4; i++)
                    ldsm_x4(af[i], ac + swz(arow + i * 16, akc));
                const int bnr = wn * 32 + ((lane >> 4) & 1) * 8 + (lane & 7);
                const int bkc = ks * 2 + ((lane >> 3) & 1);
#pragma unroll
                for (int jj = 0; jj < 2; jj++)
                    ldsm_x4(bq[jj], bc + swz(bnr + jj * 16, bkc));
#pragma unroll
                for (int i = 0; i < 4; i++)
#pragma unroll
                    for (int j = 0; j < 4; j++)
                        mma_f16(acc[i][j], af[i], &bq[j >> 1][(j & 1) * 2]);
            }
        }
    };

    if (TERMS == 1) {
        load64(0, 0);
        load64(1, 1);
        for (int ch = 0; ch < 16; ch++) {
            asm volatile("cp.async.wait_group 1;" ::: "memory");
            __syncthreads();
            if (ch + 2 < 16) load64((ch + 2) % 3, ch + 2);
            else CP_COMMIT();
            compute64(ch % 3);
        }
    } else {
        loadChunk(0, 0);
        loadChunk(1, 1);
        for (int ch = 0; ch < 32; ch++) {
            asm volatile("cp.async.wait_group 1;" ::: "memory");
            __syncthreads();
            if (ch + 2 < 32) loadChunk((ch + 2) % 3, ch + 2);
            else CP_COMMIT();
            computeChunk(ch % 3);
        }
    }

    const int gr = lane >> 2, qd = lane & 3;

    if (CLSD) {
        float p[4][2];
#pragma unroll
        for (int i = 0; i < 4; i++) { p[i][0] = 0.f; p[i][1] = 0.f; }
        const float* w2 = w2p + (long)z * H;
#pragma unroll
        for (int j = 0; j < 4; j++) {
            const long c = n0 + wn * 32 + j * 8 + qd * 2;
            const float2 w2v = *(const float2*)&w2[c];
            const float2 bv = *(const float2*)&bias[c];
#pragma unroll
            for (int i = 0; i < 4; i++) {
                const float h0 = fmaxf(acc[i][j][0] * scaleC + bv.x, 0.f);
                const float h1 = fmaxf(acc[i][j][1] * scaleC + bv.y, 0.f);
                p[i][0] += h0 * w2v.x + h1 * w2v.y;
                const float h2 = fmaxf(acc[i][j][2] * scaleC + bv.x, 0.f);
                const float h3 = fmaxf(acc[i][j][3] * scaleC + bv.y, 0.f);
                p[i][1] += h2 * w2v.x + h3 * w2v.y;
            }
        }
#pragma unroll
        for (int i = 0; i < 4; i++) {
            p[i][0] += __shfl_xor_sync(~0u, p[i][0], 1);
            p[i][0] += __shfl_xor_sync(~0u, p[i][0], 2);
            p[i][1] += __shfl_xor_sync(~0u, p[i][1], 1);
            p[i][1] += __shfl_xor_sync(~0u, p[i][1], 2);
            if (qd == 0) {
                const long r = m0 + wm * 64 + i * 16 + gr;
                atomicAdd(&C[r * S + z], p[i][0]);
                atomicAdd(&C[(r + 8) * S + z], p[i][1]);
            }
        }
    } else {
#pragma unroll
        for (int j = 0; j < 4; j++) {
            const long c = n0 + wn * 32 + j * 8 + qd * 2;
            float2 bv = make_float2(0.f, 0.f);
            if (BIAS) bv = *(const float2*)&bias[c];
#pragma unroll
            for (int i = 0; i < 4; i++) {
                const long r0 = m0 + wm * 64 + i * 16 + gr;
                float2 v0 = make_float2(acc[i][j][0] * scaleC + bv.x,
                                        acc[i][j][1] * scaleC + bv.y);
                float2 v1 = make_float2(acc[i][j][2] * scaleC + bv.x,
                                        acc[i][j][3] * scaleC + bv.y);
                if (HOUT) {
                    __half* Ch = (__half*)C;
                    *(__half2*)&Ch[r0 * ldc + c] = __floats2half2_rn(v0.x, v0.y);
                    *(__half2*)&Ch[(r0 + 8) * ldc + c] = __floats2half2_rn(v1.x, v1.y);
                } else {
                    *(float2*)&C[r0 * ldc + c] = v0;
                    *(float2*)&C[(r0 + 8) * ldc + c] = v1;
                }
            }
        }
    }
}

// =============================================================================
// conversion kernels
// =============================================================================
__global__ void split4(const float* __restrict__ src, __half* __restrict__ hi,
                       __half* __restrict__ lo, long n4, float s)
{
    const long i = (long)blockIdx.x * 256 + threadIdx.x;
    if (i >= n4) return;
    float4 v = ((const float4*)src)[i];
    __half h0, h1, h2, h3, l0, l1, l2, l3;
    hsplit(v.x, s, h0, l0);
    hsplit(v.y, s, h1, l1);
    hsplit(v.z, s, h2, l2);
    hsplit(v.w, s, h3, l3);
    __half2 a, b;
    a.x = h0; a.y = h1; b.x = h2; b.y = h3;
    ((__half2*)hi)[2 * i] = a; ((__half2*)hi)[2 * i + 1] = b;
    a.x = l0; a.y = l1; b.x = l2; b.y = l3;
    ((__half2*)lo)[2 * i] = a; ((__half2*)lo)[2 * i + 1] = b;
}

__global__ void split_hi(const float* __restrict__ src, __half* __restrict__ hi,
                         long n4)
{
    const long i = (long)blockIdx.x * 256 + threadIdx.x;
    if (i >= n4) return;
    float4 v = ((const float4*)src)[i];
    __half2 a, b;
    a.x = __float2half_rn(v.x); a.y = __float2half_rn(v.y);
    b.x = __float2half_rn(v.z); b.y = __float2half_rn(v.w);
    ((__half2*)hi)[2 * i] = a; ((__half2*)hi)[2 * i + 1] = b;
}

__global__ void tsplit(const float* __restrict__ src, __half* __restrict__ hi,
                       __half* __restrict__ lo)
{
    __shared__ float t[32][33];
    const int bx = blockIdx.x * 32, by = blockIdx.y * 32;
    const int tx = threadIdx.x;
    for (int j = threadIdx.y; j < 32; j += 8)
        t[j][tx] = src[(long)(by + j) * 1024 + bx + tx];
    __syncthreads();
    for (int j = threadIdx.y; j < 32; j += 8) {
        const long o = (long)(bx + j) * 1024 + by + tx;
        __half h, l;
        hsplit(t[tx][j], SWT, h, l);
        hi[o] = h; lo[o] = l;
    }
}

__global__ void fuse_half()
{
    const long i = (long)blockIdx.x * 256 + threadIdx.x;
    const __half2* a = (const __half2*)(g_x_hi + (long)B * D);
    const __half2* v = (const __half2*)(g_x_hi + 2L * B * D);
    __half2* f = (__half2*)g_x_hi;
#pragma unroll
    for (int j = 0; j < 4; j++) {
        float2 xf = __half22float2(a[4 * i + j]);
        float2 yf = __half22float2(v[4 * i + j]);
        f[4 * i + j] = __floats2half2_rn(0.5f * (xf.x + yf.x), 0.5f * (xf.y + yf.y));
    }
}

__global__ void misc_init(const float* __restrict__ b0, const float* __restrict__ b1,
                          const float* __restrict__ b2)
{
    const int blk = blockIdx.x;
    if (blk < 256) { g_d[blk * 256 + threadIdx.x] = 0.f; return; }
    const int i = (blk - 256) * 256 + threadIdx.x;
    if (i < 3 * F) {
        const int hh = i >> 9, j = i & 511;
        g_hbias[i] = hh == 0 ? b0[j] : (hh == 1 ? b1[j] : b2[j]);
    }
}

// =============================================================================
// bias-derived vectors
// =============================================================================
__global__ void __launch_bounds__(256) vec_pre(
    const float* __restrict__ in_proj_w, const float* __restrict__ in_proj_b,
    const float* __restrict__ out_w, const float* __restrict__ out_b)
{
    const float* wq = in_proj_w;
    const float* wk = in_proj_w + (long)D * D;
    const float* bq = in_proj_b;
    const float* bk = in_proj_b + D;
    const float* bv = in_proj_b + 2 * D;
    __shared__ float rs[3][8];
    const int t = threadIdx.x, w = t >> 5, lane = t & 31;
    const int i = blockIdx.x;
    float v0 = 0.f, v1 = 0.f, v2 = 0.f;
    if (i < D) {
        for (int e = t; e < D; e += 256) {
            v0 = fmaf(bq[e], wk[(long)e * D + i], v0);
            v1 = fmaf(bk[e], wq[(long)e * D + i], v1);
            v2 = fmaf(out_w[(long)i * D + e], bv[e], v2);
        }
    } else {
        for (int e = t; e < D; e += 256) v0 = fmaf(bq[e], bk[e], v0);
    }
#pragma unroll
    for (int o = 16; o > 0; o >>= 1) {
        v0 += __shfl_xor_sync(~0u, v0, o);
        v1 += __shfl_xor_sync(~0u, v1, o);
        v2 += __shfl_xor_sync(~0u, v2, o);
    }
    if (lane == 0) { rs[0][w] = v0; rs[1][w] = v1; rs[2][w] = v2; }
    __syncthreads();
    if (t == 0) {
        float s0 = 0.f, s1 = 0.f, s2 = 0.f;
#pragma unroll
        for (int j = 0; j < 8; j++) { s0 += rs[0][j]; s1 += rs[1][j]; s2 += rs[2][j]; }
        if (i < D) { g_vq[i] = s0; g_vk[i] = s1; g_bcomb[i] = s2 + out_b[i]; }
        else g_c0 = s0;
    }
}

// =============================================================================
// Per-batch attention — scores on HMMA (validated round 13/14)
// =============================================================================
constexpr int ATTN_SMEM = 65536 + 65536 + 8 * 32 * 33 * 4;

__global__ void __launch_bounds__(256) attn_kernel(
    const float* __restrict__ cls_b2, float* __restrict__ out)
{
    extern __shared__ char dsm[];
    const uint32_t sbase = smem_u32(dsm);
    const uint32_t QOFF = 0, QMOFF = 65536, POFF = 131072;
    float* part = (float*)(dsm + POFF);

    __shared__ float sc[32][33];
    __shared__ float vks[1024];
    __shared__ float dd[32], rk[32], wa[32], wvv[32], da[16], dv[16];

    const int b = blockIdx.x;
    const int tid = threadIdx.x, w = tid >> 5, lane = tid & 31;
    const __half* qbh = g_q_hi + (long)b * S * D;
    const __half* qmbh = g_qM_h + (long)b * S * D;

#pragma unroll
    for (int i = 0; i < 16; i++) {
        const int u = tid + 256 * i;
        const int r = (u >> 7);
        const int uu = u & 127;
        const int kc = uu >> 2, c = uu & 3;
        const long src = (long)r * D + uu * 8;
        CP16(sbase + QOFF + kc * 2048 + swz(r, c), qbh + src);
        CP16(sbase + QMOFF + kc * 2048 + swz(r, c), qmbh + src);
    }
    CP_COMMIT();
#pragma unroll
    for (int i = 0; i < 4; i++) vks[tid + 256 * i] = g_vk[tid + 256 * i];
    if (tid < 32) dd[tid] = fmaxf(g_d[b * S + tid] + cls_b2[tid], 0.f);
    asm volatile("cp.async.wait_group 0;" ::: "memory");
    __syncthreads();

    {
        float acc[2][4][4];
#pragma unroll
        for (int i = 0; i < 2; i++)
#pragma unroll
            for (int j = 0; j < 4; j++)
#pragma unroll
                for (int k = 0; k < 4; k++) acc[i][j][k] = 0.f;
#pragma unroll
        for (int cc = 0; cc < 4; cc++) {
            const uint32_t qc = sbase + QOFF + (4 * w + cc) * 2048;
            const uint32_t qmc = sbase + QMOFF + (4 * w + cc) * 2048;
#pragma unroll
            for (int ks = 0; ks < 2; ks++) {
                uint32_t af[2][4], bf[4][2];
                const int arow = lane & 15;
                const int akc = ks * 2 + (lane >> 4);
#pragma unroll
                for (int i = 0; i < 2; i++)
                    ldsm_x4(af[i], qmc + swz(i * 16 + arow, akc));
                const int brow = lane & 7;
                const int bkc = ks * 2 + ((lane >> 3) & 1);
#pragma unroll
                for (int j = 0; j < 4; j++)
                    ldsm_x2(bf[j], qc + swz(j * 8 + brow, bkc));
#pragma unroll
                for (int i = 0; i < 2; i++)
#pragma unroll
                    for (int j = 0; j < 4; j++) mma_f16(acc[i][j], af[i], bf[j]);
            }
        }
        float* pw = part + w * 1056;
        const int gr = lane >> 2, qd = lane & 3;
#pragma unroll
        for (int i = 0; i < 2; i++)
#pragma unroll
            for (int j = 0; j < 4; j++) {
                const int r = i * 16 + gr, c = j * 8 + qd * 2;
                pw[r * 33 + c] = acc[i][j][0];
                pw[r * 33 + c + 1] = acc[i][j][1];
                pw[(r + 8) * 33 + c] = acc[i][j][2];
                pw[(r + 8) * 33 + c + 1] = acc[i][j][3];
            }
    }
    __syncthreads();

#pragma unroll
    for (int i = 0; i < 4; i++) {
        const int e = tid + 256 * i;
        const int r = e >> 5, c = e & 31;
        float s = 0.f;
#pragma unroll
        for (int ww = 0; ww < 8; ww++) s += part[ww * 1056 + r * 33 + c];
        sc[r][c] = s;
    }
    {
        const int row = tid >> 3, seg = tid & 7;
        float r2 = 0.f;
        for (int j = 0; j < 128; j++) {
            const int k = seg * 128 + j;
            const uint32_t off = QOFF + (k >> 5) * 2048 + swz(row, (k >> 3) & 3) + (k & 7) * 2;
            r2 = fmaf(__half2float(*(const __half*)(dsm + off)), vks[k], r2);
        }
        r2 += __shfl_xor_sync(~0u, r2, 1);
        r2 += __shfl_xor_sync(~0u, r2, 2);
        r2 += __shfl_xor_sync(~0u, r2, 4);
        if (seg == 0) rk[row] = r2;
    }
    __syncthreads();

    const float inv_sqrtD = 0.03125f;
    for (int rr = w * 4; rr < w * 4 + 4; rr++) {
        float v = (sc[rr][lane] + rk[rr] + g_c0) * inv_sqrtD;
        float mx = v;
#pragma unroll
        for (int o = 16; o > 0; o >>= 1) mx = fmaxf(mx, __shfl_xor_sync(~0u, mx, o));
        float e = __expf(v - mx);
        float sum = e;
#pragma unroll
        for (int o = 16; o > 0; o >>= 1) sum += __shfl_xor_sync(~0u, sum, o);
        sc[rr][lane] = e / sum;
    }
    __syncthreads();

    if (tid < 32) {
        const bool isA = tid < 16;
        const int i = tid & 15;
        float v = dd[tid];
        float mx = v;
#pragma unroll
        for (int o = 8; o > 0; o >>= 1) mx = fmaxf(mx, __shfl_xor_sync(~0u, mx, o));
        float e = __expf(v - mx);
        float sum = e;
#pragma unroll
        for (int o = 8; o > 0; o >>= 1) sum += __shfl_xor_sync(~0u, sum, o);
        const float p = e / sum;
        if (isA) da[i] = p; else dv[i] = p;
        const long bse = 3L * B * F;
        if (isA) out[bse + (long)b * P + i] = p;
        else     out[bse + (long)B * P + (long)b * P + i] = p;
    }
    __syncthreads();

    if (tid < 32) {
        float a = 0.f, v2 = 0.f;
#pragma unroll
        for (int ss = 0; ss < 16; ss++) a = fmaf(da[ss], sc[ss][tid], a);
#pragma unroll
        for (int ss = 0; ss < 16; ss++) v2 = fmaf(dv[ss], sc[16 + ss][tid], v2);
        wa[tid] = a;
        wvv[tid] = v2;
    }
    __syncthreads();

#pragma unroll
    for (int i = 0; i < 4; i++) {
        const int col = tid + 256 * i;
        const uint32_t cb = QOFF + (col >> 5) * 2048;
        const int cc4 = (col >> 3) & 3;
        const int co = (col & 7) * 2;
        float a = 0.f, v2 = 0.f;
#pragma unroll
        for (int t = 0; t < 32; t++) {
            const float x = __half2float(*(const __half*)(dsm + cb + swz(t, cc4) + co));
            a = fmaf(wa[t], x, a);
            v2 = fmaf(wvv[t], x, v2);
        }
        const long ia = (long)b * D + col;
        g_qv_hi[ia] = __float2half_rn(a);
        g_qv_hi[(long)B * D + ia] = __float2half_rn(v2);
    }
}

__global__ void __launch_bounds__(128) ln_relu(
    const float* __restrict__ gm0, const float* __restrict__ be0,
    const float* __restrict__ gm1, const float* __restrict__ be1,
    const float* __restrict__ gm2, const float* __restrict__ be2,
    float* __restrict__ out)
{
    const int head = blockIdx.y, b = blockIdx.x, tid = threadIdx.x;
    const float* gm = head == 0 ? gm0 : (head == 1 ? gm1 : gm2);
    const float* be = head == 0 ? be0 : (head == 1 ? be1 : be2);
    const float* y = g_y + ((long)head * B + b) * F;

    float4 v = *(const float4*)&y[tid * 4];
    float s = v.x + v.y + v.z + v.w;
    float sq = v.x * v.x + v.y * v.y + v.z * v.z + v.w * v.w;
#pragma unroll
    for (int o = 16; o > 0; o >>= 1) {
        s += __shfl_xor_sync(~0u, s, o);
        sq += __shfl_xor_sync(~0u, sq, o);
    }
    __shared__ float ss[4], ssq[4];
    const int w = tid >> 5;
    if ((tid & 31) == 0) { ss[w] = s; ssq[w] = sq; }
    __syncthreads();
    s = ss[0] + ss[1] + ss[2] + ss[3];
    sq = ssq[0] + ssq[1] + ssq[2] + ssq[3];
    const float mean = s * (1.f / F);
    const float var = sq * (1.f / F) - mean * mean;
    const float rstd = rsqrtf(var + 1e-5f);

    float4 g4 = *(const float4*)&gm[tid * 4];
    float4 b4 = *(const float4*)&be[tid * 4];
    float4 o4;
    o4.x = fmaxf((v.x - mean) * rstd * g4.x + b4.x, 0.f);
    o4.y = fmaxf((v.y - mean) * rstd * g4.y + b4.y, 0.f);
    o4.z = fmaxf((v.z - mean) * rstd * g4.z + b4.z, 0.f);
    o4.w = fmaxf((v.w - mean) * rstd * g4.w + b4.w, 0.f);
    *(float4*)&out[((long)head * B + b) * F + tid * 4] = o4;
}

}  // namespace raff

// =============================================================================
// Launch
// =============================================================================
extern "C" void kernel_launch(void* const* d_in, const int* in_sizes, int n_in,
                              void* d_out, int out_size)
{
    using namespace raff;
    (void)in_sizes; (void)n_in; (void)out_size;

    const float* q         = (const float*)d_in[0];
    const float* in_proj_w = (const float*)d_in[1];
    const float* in_proj_b = (const float*)d_in[2];
    const float* out_w     = (const float*)d_in[3];
    const float* out_b     = (const float*)d_in[4];
    const float* cls_w1    = (const float*)d_in[5];
    const float* cls_b1    = (const float*)d_in[6];
    const float* cls_w2    = (const float*)d_in[7];
    const float* cls_b2    = (const float*)d_in[8];
    const float* fus_w     = (const float*)d_in[9];
    const float* fus_b     = (const float*)d_in[10];
    const float* fus_g     = (const float*)d_in[11];
    const float* fus_be    = (const float*)d_in[12];
    const float* pa_w      = (const float*)d_in[13];
    const float* pa_b      = (const float*)d_in[14];
    const float* pa_g      = (const float*)d_in[15];
    const float* pa_be     = (const float*)d_in[16];
    const float* pv_w      = (const float*)d_in[17];
    const float* pv_b      = (const float*)d_in[18];
    const float* pv_g      = (const float*)d_in[19];
    const float* pv_be     = (const float*)d_in[20];
    float* out = (float*)d_out;

    float *pMC, *pd, *py, *pvq, *pbcomb, *phb;
    __half *pqMh, *qhi, *w1hi, *uhi, *ulo, *vhi, *vlo,
        *mchi, *mclo, *qvhi, *xhi, *hwhi, *hwlo;
    cudaGetSymbolAddress((void**)&pMC, g_MC);
    cudaGetSymbolAddress((void**)&pqMh, g_qM_h);
    cudaGetSymbolAddress((void**)&pd, g_d);
    cudaGetSymbolAddress((void**)&py, g_y);
    cudaGetSymbolAddress((void**)&pvq, g_vq);
    cudaGetSymbolAddress((void**)&pbcomb, g_bcomb);
    cudaGetSymbolAddress((void**)&phb, g_hbias);
    cudaGetSymbolAddress((void**)&qhi, g_q_hi);
    cudaGetSymbolAddress((void**)&w1hi, g_w1_hi);
    cudaGetSymbolAddress((void**)&uhi, g_u_hi);
    cudaGetSymbolAddress((void**)&ulo, g_u_lo);
    cudaGetSymbolAddress((void**)&vhi, g_v_hi);
    cudaGetSymbolAddress((void**)&vlo, g_v_lo);
    cudaGetSymbolAddress((void**)&mchi, g_mc_hi);
    cudaGetSymbolAddress((void**)&mclo, g_mc_lo);
    cudaGetSymbolAddress((void**)&qvhi, g_qv_hi);
    cudaGetSymbolAddress((void**)&xhi, g_x_hi);
    cudaGetSymbolAddress((void**)&hwhi, g_hw_hi);
    cudaGetSymbolAddress((void**)&hwlo, g_hw_lo);

    cudaFuncSetAttribute((const void*)bsgemm<3, false, false, false>,
                         cudaFuncAttributeMaxDynamicSharedMemorySize, GEMM_SMEM);
    cudaFuncSetAttribute((const void*)bsgemm<2, true, false, true>,
                         cudaFuncAttributeMaxDynamicSharedMemorySize, GEMM_SMEM);
    cudaFuncSetAttribute((const void*)bsgemm<2, true, false, false>,
                         cudaFuncAttributeMaxDynamicSharedMemorySize, GEMM_SMEM);
    cudaFuncSetAttribute((const void*)bsgemm<1, true, false, true>,
                         cudaFuncAttributeMaxDynamicSharedMemorySize, GEMM_SMEM);
    cudaFuncSetAttribute((const void*)bsgemm<1, false, true, false>,
                         cudaFuncAttributeMaxDynamicSharedMemorySize, GEMM_SMEM);
    cudaFuncSetAttribute((const void*)attn_kernel,
                         cudaFuncAttributeMaxDynamicSharedMemorySize, ATTN_SMEM);

    static cudaStream_t s1 = nullptr;
    static cudaEvent_t ef = nullptr, epre = nullptr, ecls = nullptr;
    if (!s1) {
        cudaStreamCreateWithFlags(&s1, cudaStreamNonBlocking);
        cudaEventCreateWithFlags(&ef, cudaEventDisableTiming);
        cudaEventCreateWithFlags(&epre, cudaEventDisableTiming);
        cudaEventCreateWithFlags(&ecls, cudaEventDisableTiming);
    }

    // ---- fork: independent weight conversions on side stream ----
    cudaEventRecord(ef, 0);
    cudaStreamWaitEvent(s1, ef, 0);
    split_hi<<<(int)((long)S * H * D / 4 / 256), 256, 0, s1>>>(
        cls_w1, w1hi, (long)S * H * D / 4);
    split4<<<F * D / 4 / 256, 256, 0, s1>>>(fus_w, hwhi, hwlo, (long)F * D / 4, SWT);
    split4<<<F * D / 4 / 256, 256, 0, s1>>>(pa_w, hwhi + (long)F * D,
                                            hwlo + (long)F * D, (long)F * D / 4, SWT);
    split4<<<F * D / 4 / 256, 256, 0, s1>>>(pv_w, hwhi + 2L * F * D,
                                            hwlo + 2L * F * D, (long)F * D / 4, SWT);

    // ---- main stream: critical path (round-14 order) ----
    vec_pre<<<D + 1, 256>>>(in_proj_w, in_proj_b, out_w, out_b);
    misc_init<<<262, 256>>>(fus_b, pa_b, pv_b);
    split_hi<<<(int)(NQ / 4 / 256), 256>>>(q, qhi, NQ / 4);
    split4<<<D * D / 4 / 256, 256>>>(out_w, uhi + (long)D * D, ulo + (long)D * D,
                                     D * D / 4, SWT);
    tsplit<<<dim3(32, 32), dim3(32, 8)>>>(in_proj_w + (long)D * D, uhi, ulo);    // WkT
    tsplit<<<dim3(32, 32), dim3(32, 8)>>>(in_proj_w, vhi, vlo);                  // WqT
    tsplit<<<dim3(32, 32), dim3(32, 8)>>>(in_proj_w + 2L * D * D,
                                          vhi + (long)D * D, vlo + (long)D * D); // WvT

    bsgemm<3, false, false, false><<<dim3(8, 8, 2), 256, GEMM_SMEM>>>(
        uhi, ulo, D, (long)D * D, vhi, vlo, (long)D * D,
        pMC, D, (long)D * D, nullptr, 0L, nullptr, SC_WW);
    split4<<<2 * D * D / 4 / 256, 256>>>(pMC, mchi, mclo, 2 * D * D / 4, SWT);
    cudaEventRecord(epre, 0);   // qhi + mc ready; g_d zeroed; precedes qM

    // ---- concurrent tensor GEMMs: qM (main) || cls (side) ----
    bsgemm<1, true, false, true><<<dim3(8, 512), 256, GEMM_SMEM>>>(
        qhi, nullptr, (long)D, 0L, mchi, nullptr, 0L, (float*)pqMh, D, 0L,
        pvq, 0L, nullptr, SC_QW);

    cudaStreamWaitEvent(s1, epre, 0);
    bsgemm<1, false, true, false><<<dim3(4, 16, 32), 256, GEMM_SMEM, s1>>>(
        qhi, nullptr, (long)S * D, (long)D, w1hi, nullptr, (long)H * D,
        pd, S, 0L, cls_b1, (long)H, cls_w2, 1.f);
    cudaEventRecord(ecls, s1);

    // ---- join: attn needs qM (main) + d (side) ----
    cudaStreamWaitEvent(0, ecls, 0);
    attn_kernel<<<B, 256, ATTN_SMEM>>>(cls_b2, out);

    // [audio; video] = qv * Cov^T + bcomb  (2-term, fp16 out -> x_hi[B*D..3B*D))
    bsgemm<2, true, false, true><<<dim3(8, 32), 256, GEMM_SMEM>>>(
        qvhi, nullptr, (long)D, 0L, mchi + (long)D * D, mclo + (long)D * D, 0L,
        (float*)(xhi + (long)B * D), D, 0L, pbcomb, 0L, nullptr, SC_QW);

    fuse_half<<<(int)((long)B * D / 8 / 256), 256>>>();

    // heads (hw conversions on s1 precede cls, ordered via ecls wait)
    bsgemm<2, true, false, false><<<dim3(4, 16, 3), 256, GEMM_SMEM>>>(
        xhi, nullptr, (long)D, (long)B * D, hwhi, hwlo, (long)F * D,
        py, F, (long)B * F, phb, (long)F, nullptr, SC_QW);

    ln_relu<<<dim3(B, 3), 128>>>(fus_g, fus_be, pa_g, pa_be, pv_g, pv_be, out);
}

// round 17
// speedup vs baseline: 1.0670x; 1.0562x over previous
#include <cuda_runtime.h>
#include <cuda_fp16.h>
#include <cstdint>

// =============================================================================
// RAFF_8555574853896 — round 17: score contraction fused into the qM GEMM
// epilogue (atomicAdd partial 32x32 score tiles; qM never touches DRAM).
// attn shrinks to q-tile load + scores + softmax + weighted sums.
//
// Algebra:
//   scores = q Mt^T q^T / sqrt(D) + rank-1 bias,  Mt = (Wq^T Wk)^T
//   audio  = (w_a^T q) Cov^T + bcomb,             Cov = out_w Wv
// =============================================================================

namespace raff {

constexpr int B = 2048, S = 32, P = 16, D = 1024, H = 512, F = 512;
constexpr long NQ = (long)B * S * D;

constexpr float SWT = 32.f;
constexpr float SC_QW = 1.f / SWT;
constexpr float SC_WW = 1.f / (SWT * SWT);

// ---------------- static device scratch ----------------
__device__ float g_vq[D], g_vk[D], g_bcomb[D];
__device__ float g_c0;
__device__ float g_MC[2 * D * D];              // [Mt; Cov] fp32
__device__ float g_d[B * S];
__device__ float g_scores[(long)B * S * S];    // fp32 score accumulators (8 MB)
__device__ float g_y[3L * B * F];
__device__ float g_hbias[3 * F];

__device__ __half g_q_hi[NQ];
__device__ __half g_w1_hi[(long)S * H * D];
__device__ __half g_u_hi[2 * D * D], g_u_lo[2 * D * D];    // [WkT; out_w] x32
__device__ __half g_v_hi[2 * D * D], g_v_lo[2 * D * D];    // [WqT; WvT] x32
__device__ __half g_mc_hi[2 * D * D], g_mc_lo[2 * D * D];  // [Mt; Cov] x32
__device__ __half g_qv_hi[2L * B * D];
__device__ __half g_x_hi[3L * B * D];          // fusion | audio | video
__device__ __half g_hw_hi[3L * F * D], g_hw_lo[3L * F * D];

// ---------------- PTX helpers (base sm_103-legal) ----------------
__device__ __forceinline__ uint32_t smem_u32(const void* p) {
    uint32_t a;
    asm("{ .reg .u64 t; cvta.to.shared.u64 t, %1; cvt.u32.u64 %0, t; }"
        : "=r"(a) : "l"(p));
    return a;
}
#define CP16(dst, src) \
    asm volatile("cp.async.cg.shared.global [%0], [%1], 16;" :: "r"(dst), "l"(src))
#define CP_COMMIT() asm volatile("cp.async.commit_group;" ::: "memory")

__device__ __forceinline__ void ldsm_x4(uint32_t* r, uint32_t addr) {
    asm volatile("ldmatrix.sync.aligned.m8n8.x4.shared.b16 {%0,%1,%2,%3}, [%4];"
                 : "=r"(r[0]), "=r"(r[1]), "=r"(r[2]), "=r"(r[3]) : "r"(addr));
}
__device__ __forceinline__ void ldsm_x2(uint32_t* r, uint32_t addr) {
    asm volatile("ldmatrix.sync.aligned.m8n8.x2.shared.b16 {%0,%1}, [%2];"
                 : "=r"(r[0]), "=r"(r[1]) : "r"(addr));
}
__device__ __forceinline__ void mma_f16(float* c, const uint32_t* a, const uint32_t* b) {
    asm volatile(
        "mma.sync.aligned.m16n8k16.row.col.f32.f16.f16.f32 "
        "{%0,%1,%2,%3}, {%4,%5,%6,%7}, {%8,%9}, {%0,%1,%2,%3};"
        : "+f"(c[0]), "+f"(c[1]), "+f"(c[2]), "+f"(c[3])
        : "r"(a[0]), "r"(a[1]), "r"(a[2]), "r"(a[3]), "r"(b[0]), "r"(b[1]));
}

__device__ __forceinline__ uint32_t swz(int r, int c) {
    return (uint32_t)((r * 4 + (c ^ ((r >> 1) & 3))) * 16);
}

__device__ __forceinline__ void hsplit(float x, float s, __half& hi, __half& lo) {
    const float xs = x * s;
    hi = __float2half_rn(xs);
    lo = __float2half_rn(xs - __half2float(hi));
}

// =============================================================================
// fp16 split GEMM. Block 128x128, 8 warps (2m x 4n), warp 64x32, 3 stages.
// TERMS==1: K-chunk 64 + x4 B loads.  TERMS>=2: K-chunk 32.
// SCORES: fused partial score contraction in epilogue (C = scores buffer,
//         qsc = g_q_hi; per-block 32x32x128 MMAs + atomicAdd).
// =============================================================================
constexpr int STAGE = 32768;
constexpr int NSTG = 3;
constexpr int GEMM_SMEM = NSTG * STAGE;

template <int TERMS, bool BIAS, bool CLSD, bool HOUT, bool SCORES>
__global__ void __launch_bounds__(256, 2) bsgemm(
    const __half* __restrict__ Ahi, const __half* __restrict__ Alo,
    long lda, long aOffZ,
    const __half* __restrict__ Bhi, const __half* __restrict__ Blo,
    long bOffZ,
    float* __restrict__ C, int ldc, long cOffZ,
    const float* __restrict__ bias, long biasOffZ,
    const float* __restrict__ w2p, float scaleC,
    const __half* __restrict__ qsc)
{
    extern __shared__ char dsm[];
    const uint32_t base = smem_u32(dsm);

    const int tid = threadIdx.x, lane = tid & 31, w = tid >> 5;
    const int wm = w & 1, wn = w >> 1;
    const int z = blockIdx.z;
    const long m0 = (long)blockIdx.y * 128;
    const long n0 = (long)blockIdx.x * 128;
    Ahi += z * aOffZ;
    if (TERMS >= 3) Alo += z * aOffZ;
    Bhi += z * bOffZ;
    if (TERMS >= 2) Blo += z * bOffZ;
    C += z * cOffZ;
    if (BIAS || CLSD) bias += z * biasOffZ;

    float acc[4][4][4];
#pragma unroll
    for (int i = 0; i < 4; i++)
#pragma unroll
        for (int j = 0; j < 4; j++)
#pragma unroll
            for (int k = 0; k < 4; k++) acc[i][j][k] = 0.f;

    auto loadChunk = [&](int s, int kc) {
        const long k0 = (long)kc * 32;
        const uint32_t ah = base + s * STAGE;
        const uint32_t al = ah + 8192;
        const uint32_t bh = ah + 16384;
        const uint32_t bl = ah + 24576;
#pragma unroll
        for (int i = 0; i < 2; i++) {
            const int idx = tid + 256 * i;
            const int r = idx >> 2, c = idx & 3;
            const uint32_t dst = swz(r, c);
            const long offA = (m0 + r) * lda + k0 + c * 8;
            CP16(ah + dst, Ahi + offA);
            if (TERMS >= 3) CP16(al + dst, Alo + offA);
            const long offB = (n0 + r) * 1024 + k0 + c * 8;
            CP16(bh + dst, Bhi + offB);
            if (TERMS >= 2) CP16(bl + dst, Blo + offB);
        }
        CP_COMMIT();
    };

    auto computeChunk = [&](int s) {
        const uint32_t ah = base + s * STAGE;
        const uint32_t al = ah + 8192;
        const uint32_t bh = ah + 16384;
        const uint32_t bl = ah + 24576;
#pragma unroll
        for (int ks = 0; ks < 2; ks++) {
            uint32_t afh[4][4], afl[4][4], bf[4][2];
            const int arow = wm * 64 + (lane & 15);
            const int akc = ks * 2 + (lane >> 4);
#pragma unroll
            for (int i = 0; i < 4; i++) {
                const uint32_t off = swz(arow + i * 16, akc);
                ldsm_x4(afh[i], ah + off);
                if (TERMS >= 3) ldsm_x4(afl[i], al + off);
            }
            const int brow = wn * 32 + (lane & 7);
            const int bkc = ks * 2 + ((lane >> 3) & 1);
#pragma unroll
            for (int j = 0; j < 4; j++)
                ldsm_x2(bf[j], bh + swz(brow + j * 8, bkc));
#pragma unroll
            for (int i = 0; i < 4; i++)
#pragma unroll
                for (int j = 0; j < 4; j++) mma_f16(acc[i][j], afh[i], bf[j]);
            if (TERMS >= 3) {
#pragma unroll
                for (int i = 0; i < 4; i++)
#pragma unroll
                    for (int j = 0; j < 4; j++) mma_f16(acc[i][j], afl[i], bf[j]);
            }
            if (TERMS >= 2) {
#pragma unroll
                for (int j = 0; j < 4; j++)
                    ldsm_x2(bf[j], bl + swz(brow + j * 8, bkc));
#pragma unroll
                for (int i = 0; i < 4; i++)
#pragma unroll
                    for (int j = 0; j < 4; j++) mma_f16(acc[i][j], afh[i], bf[j]);
            }
        }
    };

    auto load64 = [&](int s, int kc) {
        const long k0 = (long)kc * 64;
        const uint32_t ah = base + s * STAGE;
        const uint32_t bh = ah + 16384;
#pragma unroll
        for (int i = 0; i < 4; i++) {
            const int u = tid + 256 * i;
            const int r = u >> 3, uu = u & 7;
            const int sub = uu >> 2, c = uu & 3;
            const uint32_t dst = sub * 8192 + swz(r, c);
            CP16(ah + dst, Ahi + (m0 + r) * lda + k0 + uu * 8);
            CP16(bh + dst, Bhi + (n0 + r) * 1024 + k0 + uu * 8);
        }
        CP_COMMIT();
    };

    auto compute64 = [&](int s) {
        const uint32_t ah = base + s * STAGE;
        const uint32_t bh = ah + 16384;
#pragma unroll
        for (int sub = 0; sub < 2; sub++) {
            const uint32_t ac = ah + sub * 8192;
            const uint32_t bc = bh + sub * 8192;
#pragma unroll
            for (int ks = 0; ks < 2; ks++) {
                uint32_t af[4][4], bq[2][4];
                const int arow = wm * 64 + (lane & 15);
                const int akc = ks * 2 + (lane >> 4);
#pragma unroll
                for (int i = 0; i < 4; i++)
                    ldsm_x4(af[i], ac + swz(arow + i * 16, akc));
                const int bnr = wn * 32 + ((lane >> 4) & 1) * 8 + (lane & 7);
                const int bkc = ks * 2 + ((lane >> 3) & 1);
#pragma unroll
                for (int jj = 0; jj < 2; jj++)
                    ldsm_x4(bq[jj], bc + swz(bnr + jj * 16, bkc));
#pragma unroll
                for (int i = 0; i < 4; i++)
#pragma unroll
                    for (int j = 0; j < 4; j++)
                        mma_f16(acc[i][j], af[i], &bq[j >> 1][(j & 1) * 2]);
            }
        }
    };

    if (TERMS == 1) {
        load64(0, 0);
        load64(1, 1);
        for (int ch = 0; ch < 16; ch++) {
            asm volatile("cp.async.wait_group 1;" ::: "memory");
            __syncthreads();
            if (ch + 2 < 16) load64((ch + 2) % 3, ch + 2);
            else CP_COMMIT();
            compute64(ch % 3);
        }
    } else {
        loadChunk(0, 0);
        loadChunk(1, 1);
        for (int ch = 0; ch < 32; ch++) {
            asm volatile("cp.async.wait_group 1;" ::: "memory");
            __syncthreads();
            if (ch + 2 < 32) loadChunk((ch + 2) % 3, ch + 2);
            else CP_COMMIT();
            computeChunk(ch % 3);
        }
    }

    const int gr = lane >> 2, qd = lane & 3;

    if (SCORES) {
        // ---- fused partial scores: S_b += Ctile_b . q_b^T over this D-slice
        const uint32_t ct = base;            // 32 KB: chunks (rg, kc) 2048B
        const uint32_t qt = base + 32768;    // 32 KB: 4 batches x 4 kchunks
        __syncthreads();                     // main-loop smem reads done

        // issue q loads for the 4 batches over cols n0..n0+127
#pragma unroll
        for (int i = 0; i < 8; i++) {
            const int u = tid + 256 * i;     // 0..2047 16B units
            const int bb = u >> 9, uu = u & 511;
            const int r = uu >> 4, un = uu & 15;
            const int kc = un >> 2, c = un & 3;
            const long src = ((m0 >> 5) + bb) * (long)S * D + (long)r * D + n0 + un * 8;
            CP16(qt + bb * 8192 + kc * 2048 + swz(r, c), qsc + src);
        }
        CP_COMMIT();

        // store biased C tile as fp16 into ct (swizzled 32-row chunks)
#pragma unroll
        for (int j = 0; j < 4; j++) {
            const int wc = wn * 32 + j * 8 + qd * 2;
            const float2 bv = *(const float2*)&bias[n0 + wc];
            const int kc = wc >> 5, c4 = (wc >> 3) & 3, co = (wc & 7) * 2;
#pragma unroll
            for (int i = 0; i < 4; i++) {
                const int r0 = wm * 64 + i * 16 + gr;
                float2 v0 = make_float2(acc[i][j][0] * scaleC + bv.x,
                                        acc[i][j][1] * scaleC + bv.y);
                float2 v1 = make_float2(acc[i][j][2] * scaleC + bv.x,
                                        acc[i][j][3] * scaleC + bv.y);
                const uint32_t ch0 = ct + ((r0 >> 5) * 4 + kc) * 2048;
                *(__half2*)(dsm + (ch0 - base) + swz(r0 & 31, c4) + co) =
                    __floats2half2_rn(v0.x, v0.y);
                const int r1 = r0 + 8;
                const uint32_t ch1 = ct + ((r1 >> 5) * 4 + kc) * 2048;
                *(__half2*)(dsm + (ch1 - base) + swz(r1 & 31, c4) + co) =
                    __floats2half2_rn(v1.x, v1.y);
            }
        }
        asm volatile("cp.async.wait_group 0;" ::: "memory");
        __syncthreads();

        // warp w: batch bb = w>>1, rows hh*16..+15; 32 MMAs over K=128
        const int bb = w >> 1, hh = w & 1;
        float sa[4][4];
#pragma unroll
        for (int j = 0; j < 4; j++)
#pragma unroll
            for (int k = 0; k < 4; k++) sa[j][k] = 0.f;
#pragma unroll
        for (int kc = 0; kc < 4; kc++) {
            const uint32_t cch = ct + (bb * 4 + kc) * 2048;
            const uint32_t qch = qt + bb * 8192 + kc * 2048;
#pragma unroll
            for (int ks = 0; ks < 2; ks++) {
                uint32_t af[4], bf[4][2];
                ldsm_x4(af, cch + swz(hh * 16 + (lane & 15), ks * 2 + (lane >> 4)));
                const int brow = lane & 7;
                const int bkc = ks * 2 + ((lane >> 3) & 1);
#pragma unroll
                for (int j = 0; j < 4; j++)
                    ldsm_x2(bf[j], qch + swz(j * 8 + brow, bkc));
#pragma unroll
                for (int j = 0; j < 4; j++) mma_f16(sa[j], af, bf[j]);
            }
        }
        float* Sb = C + ((m0 >> 5) + bb) * 1024;
#pragma unroll
        for (int j = 0; j < 4; j++) {
            const int r = hh * 16 + gr, c = j * 8 + qd * 2;
            atomicAdd(&Sb[r * 32 + c], sa[j][0]);
            atomicAdd(&Sb[r * 32 + c + 1], sa[j][1]);
            atomicAdd(&Sb[(r + 8) * 32 + c], sa[j][2]);
            atomicAdd(&Sb[(r + 8) * 32 + c + 1], sa[j][3]);
        }
    } else if (CLSD) {
        float p[4][2];
#pragma unroll
        for (int i = 0; i < 4; i++) { p[i][0] = 0.f; p[i][1] = 0.f; }
        const float* w2 = w2p + (long)z * H;
#pragma unroll
        for (int j = 0; j < 4; j++) {
            const long c = n0 + wn * 32 + j * 8 + qd * 2;
            const float2 w2v = *(const float2*)&w2[c];
            const float2 bv = *(const float2*)&bias[c];
#pragma unroll
            for (int i = 0; i < 4; i++) {
                const float h0 = fmaxf(acc[i][j][0] * scaleC + bv.x, 0.f);
                const float h1 = fmaxf(acc[i][j][1] * scaleC + bv.y, 0.f);
                p[i][0] += h0 * w2v.x + h1 * w2v.y;
                const float h2 = fmaxf(acc[i][j][2] * scaleC + bv.x, 0.f);
                const float h3 = fmaxf(acc[i][j][3] * scaleC + bv.y, 0.f);
                p[i][1] += h2 * w2v.x + h3 * w2v.y;
            }
        }
#pragma unroll
        for (int i = 0; i < 4; i++) {
            p[i][0] += __shfl_xor_sync(~0u, p[i][0], 1);
            p[i][0] += __shfl_xor_sync(~0u, p[i][0], 2);
            p[i][1] += __shfl_xor_sync(~0u, p[i][1], 1);
            p[i][1] += __shfl_xor_sync(~0u, p[i][1], 2);
            if (qd == 0) {
                const long r = m0 + wm * 64 + i * 16 + gr;
                atomicAdd(&C[r * S + z], p[i][0]);
                atomicAdd(&C[(r + 8) * S + z], p[i][1]);
            }
        }
    } else {
#pragma unroll
        for (int j = 0; j < 4; j++) {
            const long c = n0 + wn * 32 + j * 8 + qd * 2;
            float2 bv = make_float2(0.f, 0.f);
            if (BIAS) bv = *(const float2*)&bias[c];
#pragma unroll
            for (int i = 0; i < 4; i++) {
                const long r0 = m0 + wm * 64 + i * 16 + gr;
                float2 v0 = make_float2(acc[i][j][0] * scaleC + bv.x,
                                        acc[i][j][1] * scaleC + bv.y);
                float2 v1 = make_float2(acc[i][j][2] * scaleC + bv.x,
                                        acc[i][j][3] * scaleC + bv.y);
                if (HOUT) {
                    __half* Ch = (__half*)C;
                    *(__half2*)&Ch[r0 * ldc + c] = __floats2half2_rn(v0.x, v0.y);
                    *(__half2*)&Ch[(r0 + 8) * ldc + c] = __floats2half2_rn(v1.x, v1.y);
                } else {
                    *(float2*)&C[r0 * ldc + c] = v0;
                    *(float2*)&C[(r0 + 8) * ldc + c] = v1;
                }
            }
        }
    }
}

// =============================================================================
// conversion kernels
// =============================================================================
__global__ void split4(const float* __restrict__ src, __half* __restrict__ hi,
                       __half* __restrict__ lo, long n4, float s)
{
    const long i = (long)blockIdx.x * 256 + threadIdx.x;
    if (i >= n4) return;
    float4 v = ((const float4*)src)[i];
    __half h0, h1, h2, h3, l0, l1, l2, l3;
    hsplit(v.x, s, h0, l0);
    hsplit(v.y, s, h1, l1);
    hsplit(v.z, s, h2, l2);
    hsplit(v.w, s, h3, l3);
    __half2 a, b;
    a.x = h0; a.y = h1; b.x = h2; b.y = h3;
    ((__half2*)hi)[2 * i] = a; ((__half2*)hi)[2 * i + 1] = b;
    a.x = l0; a.y = l1; b.x = l2; b.y = l3;
    ((__half2*)lo)[2 * i] = a; ((__half2*)lo)[2 * i + 1] = b;
}

__global__ void split_hi(const float* __restrict__ src, __half* __restrict__ hi,
                         long n4)
{
    const long i = (long)blockIdx.x * 256 + threadIdx.x;
    if (i >= n4) return;
    float4 v = ((const float4*)src)[i];
    __half2 a, b;
    a.x = __float2half_rn(v.x); a.y = __float2half_rn(v.y);
    b.x = __float2half_rn(v.z); b.y = __float2half_rn(v.w);
    ((__half2*)hi)[2 * i] = a; ((__half2*)hi)[2 * i + 1] = b;
}

__global__ void tsplit(const float* __restrict__ src, __half* __restrict__ hi,
                       __half* __restrict__ lo)
{
    __shared__ float t[32][33];
    const int bx = blockIdx.x * 32, by = blockIdx.y * 32;
    const int tx = threadIdx.x;
    for (int j = threadIdx.y; j < 32; j += 8)
        t[j][tx] = src[(long)(by + j) * 1024 + bx + tx];
    __syncthreads();
    for (int j = threadIdx.y; j < 32; j += 8) {
        const long o = (long)(bx + j) * 1024 + by + tx;
        __half h, l;
        hsplit(t[tx][j], SWT, h, l);
        hi[o] = h; lo[o] = l;
    }
}

__global__ void fuse_half()
{
    const long i = (long)blockIdx.x * 256 + threadIdx.x;
    const __half2* a = (const __half2*)(g_x_hi + (long)B * D);
    const __half2* v = (const __half2*)(g_x_hi + 2L * B * D);
    __half2* f = (__half2*)g_x_hi;
#pragma unroll
    for (int j = 0; j < 4; j++) {
        float2 xf = __half22float2(a[4 * i + j]);
        float2 yf = __half22float2(v[4 * i + j]);
        f[4 * i + j] = __floats2half2_rn(0.5f * (xf.x + yf.x), 0.5f * (xf.y + yf.y));
    }
}

// zero g_d (256) + pack head biases (6) + zero g_scores (8192)
__global__ void misc_init(const float* __restrict__ b0, const float* __restrict__ b1,
                          const float* __restrict__ b2)
{
    const int blk = blockIdx.x;
    if (blk < 256) { g_d[blk * 256 + threadIdx.x] = 0.f; return; }
    if (blk < 262) {
        const int i = (blk - 256) * 256 + threadIdx.x;
        if (i < 3 * F) {
            const int hh = i >> 9, j = i & 511;
            g_hbias[i] = hh == 0 ? b0[j] : (hh == 1 ? b1[j] : b2[j]);
        }
        return;
    }
    const long zi = (long)(blk - 262) * 256 + threadIdx.x;
    g_scores[zi] = 0.f;
}

// =============================================================================
// bias-derived vectors
// =============================================================================
__global__ void __launch_bounds__(256) vec_pre(
    const float* __restrict__ in_proj_w, const float* __restrict__ in_proj_b,
    const float* __restrict__ out_w, const float* __restrict__ out_b)
{
    const float* wq = in_proj_w;
    const float* wk = in_proj_w + (long)D * D;
    const float* bq = in_proj_b;
    const float* bk = in_proj_b + D;
    const float* bv = in_proj_b + 2 * D;
    __shared__ float rs[3][8];
    const int t = threadIdx.x, w = t >> 5, lane = t & 31;
    const int i = blockIdx.x;
    float v0 = 0.f, v1 = 0.f, v2 = 0.f;
    if (i < D) {
        for (int e = t; e < D; e += 256) {
            v0 = fmaf(bq[e], wk[(long)e * D + i], v0);
            v1 = fmaf(bk[e], wq[(long)e * D + i], v1);
            v2 = fmaf(out_w[(long)i * D + e], bv[e], v2);
        }
    } else {
        for (int e = t; e < D; e += 256) v0 = fmaf(bq[e], bk[e], v0);
    }
#pragma unroll
    for (int o = 16; o > 0; o >>= 1) {
        v0 += __shfl_xor_sync(~0u, v0, o);
        v1 += __shfl_xor_sync(~0u, v1, o);
        v2 += __shfl_xor_sync(~0u, v2, o);
    }
    if (lane == 0) { rs[0][w] = v0; rs[1][w] = v1; rs[2][w] = v2; }
    __syncthreads();
    if (t == 0) {
        float s0 = 0.f, s1 = 0.f, s2 = 0.f;
#pragma unroll
        for (int j = 0; j < 8; j++) { s0 += rs[0][j]; s1 += rs[1][j]; s2 += rs[2][j]; }
        if (i < D) { g_vq[i] = s0; g_vk[i] = s1; g_bcomb[i] = s2 + out_b[i]; }
        else g_c0 = s0;
    }
}

// =============================================================================
// Per-batch attention — scores precomputed in g_scores; q tile for rk +
// weighted sums.
// =============================================================================
constexpr int ATTN_SMEM = 65536;

__global__ void __launch_bounds__(256) attn_kernel(
    const float* __restrict__ cls_b2, float* __restrict__ out)
{
    extern __shared__ char dsm[];
    const uint32_t sbase = smem_u32(dsm);

    __shared__ float sc[32][33];
    __shared__ float vks[1024];
    __shared__ float dd[32], rk[32], wa[32], wvv[32], da[16], dv[16];

    const int b = blockIdx.x;
    const int tid = threadIdx.x, w = tid >> 5, lane = tid & 31;
    const __half* qbh = g_q_hi + (long)b * S * D;

#pragma unroll
    for (int i = 0; i < 8; i++) {
        const int u = tid + 256 * i;
        const int r = (u >> 6);               // 0..31 (64 units/row)
        const int uu = u & 63;                // col unit
        const int kc = uu >> 2, c = uu & 3;   // wait: 128 units/row for 1024 cols
        // NOTE: 1024 cols * 2B = 2048B per row = 128 units; use 16 iterations
        (void)r; (void)uu; (void)kc; (void)c;
        break;
    }
    // q tile: 32 rows x 1024 cols fp16 = 64 KB = 4096 units, 16 per thread
#pragma unroll
    for (int i = 0; i < 16; i++) {
        const int u = tid + 256 * i;
        const int r = (u >> 7);
        const int uu = u & 127;
        const int kc = uu >> 2, c = uu & 3;
        CP16(sbase + kc * 2048 + swz(r, c), qbh + (long)r * D + uu * 8);
    }
    CP_COMMIT();
#pragma unroll
    for (int i = 0; i < 4; i++) vks[tid + 256 * i] = g_vk[tid + 256 * i];
#pragma unroll
    for (int i = 0; i < 4; i++) {
        const int e = tid + 256 * i;
        sc[e >> 5][e & 31] = g_scores[(long)b * 1024 + e];
    }
    if (tid < 32) dd[tid] = fmaxf(g_d[b * S + tid] + cls_b2[tid], 0.f);
    asm volatile("cp.async.wait_group 0;" ::: "memory");
    __syncthreads();

    // rk = q . vk (8 threads/row, 128 k each)
    {
        const int row = tid >> 3, seg = tid & 7;
        float r2 = 0.f;
        for (int j = 0; j < 128; j++) {
            const int k = seg * 128 + j;
            const uint32_t off = (k >> 5) * 2048 + swz(row, (k >> 3) & 3) + (k & 7) * 2;
            r2 = fmaf(__half2float(*(const __half*)(dsm + off)), vks[k], r2);
        }
        r2 += __shfl_xor_sync(~0u, r2, 1);
        r2 += __shfl_xor_sync(~0u, r2, 2);
        r2 += __shfl_xor_sync(~0u, r2, 4);
        if (seg == 0) rk[row] = r2;
    }
    __syncthreads();

    const float inv_sqrtD = 0.03125f;
    for (int rr = w * 4; rr < w * 4 + 4; rr++) {
        float v = (sc[rr][lane] + rk[rr] + g_c0) * inv_sqrtD;
        float mx = v;
#pragma unroll
        for (int o = 16; o > 0; o >>= 1) mx = fmaxf(mx, __shfl_xor_sync(~0u, mx, o));
        float e = __expf(v - mx);
        float sum = e;
#pragma unroll
        for (int o = 16; o > 0; o >>= 1) sum += __shfl_xor_sync(~0u, sum, o);
        sc[rr][lane] = e / sum;
    }
    __syncthreads();

    if (tid < 32) {
        const bool isA = tid < 16;
        const int i = tid & 15;
        float v = dd[tid];
        float mx = v;
#pragma unroll
        for (int o = 8; o > 0; o >>= 1) mx = fmaxf(mx, __shfl_xor_sync(~0u, mx, o));
        float e = __expf(v - mx);
        float sum = e;
#pragma unroll
        for (int o = 8; o > 0; o >>= 1) sum += __shfl_xor_sync(~0u, sum, o);
        const float p = e / sum;
        if (isA) da[i] = p; else dv[i] = p;
        const long bse = 3L * B * F;
        if (isA) out[bse + (long)b * P + i] = p;
        else     out[bse + (long)B * P + (long)b * P + i] = p;
    }
    __syncthreads();

    if (tid < 32) {
        float a = 0.f, v2 = 0.f;
#pragma unroll
        for (int ss = 0; ss < 16; ss++) a = fmaf(da[ss], sc[ss][tid], a);
#pragma unroll
        for (int ss = 0; ss < 16; ss++) v2 = fmaf(dv[ss], sc[16 + ss][tid], v2);
        wa[tid] = a;
        wvv[tid] = v2;
    }
    __syncthreads();

#pragma unroll
    for (int i = 0; i < 4; i++) {
        const int col = tid + 256 * i;
        const uint32_t cb = (col >> 5) * 2048;
        const int cc4 = (col >> 3) & 3;
        const int co = (col & 7) * 2;
        float a = 0.f, v2 = 0.f;
#pragma unroll
        for (int t = 0; t < 32; t++) {
            const float x = __half2float(*(const __half*)(dsm + cb + swz(t, cc4) + co));
            a = fmaf(wa[t], x, a);
            v2 = fmaf(wvv[t], x, v2);
        }
        const long ia = (long)b * D + col;
        g_qv_hi[ia] = __float2half_rn(a);
        g_qv_hi[(long)B * D + ia] = __float2half_rn(v2);
    }
}

__global__ void __launch_bounds__(128) ln_relu(
    const float* __restrict__ gm0, const float* __restrict__ be0,
    const float* __restrict__ gm1, const float* __restrict__ be1,
    const float* __restrict__ gm2, const float* __restrict__ be2,
    float* __restrict__ out)
{
    const int head = blockIdx.y, b = blockIdx.x, tid = threadIdx.x;
    const float* gm = head == 0 ? gm0 : (head == 1 ? gm1 : gm2);
    const float* be = head == 0 ? be0 : (head == 1 ? be1 : be2);
    const float* y = g_y + ((long)head * B + b) * F;

    float4 v = *(const float4*)&y[tid * 4];
    float s = v.x + v.y + v.z + v.w;
    float sq = v.x * v.x + v.y * v.y + v.z * v.z + v.w * v.w;
#pragma unroll
    for (int o = 16; o > 0; o >>= 1) {
        s += __shfl_xor_sync(~0u, s, o);
        sq += __shfl_xor_sync(~0u, sq, o);
    }
    __shared__ float ss[4], ssq[4];
    const int w = tid >> 5;
    if ((tid & 31) == 0) { ss[w] = s; ssq[w] = sq; }
    __syncthreads();
    s = ss[0] + ss[1] + ss[2] + ss[3];
    sq = ssq[0] + ssq[1] + ssq[2] + ssq[3];
    const float mean = s * (1.f / F);
    const float var = sq * (1.f / F) - mean * mean;
    const float rstd = rsqrtf(var + 1e-5f);

    float4 g4 = *(const float4*)&gm[tid * 4];
    float4 b4 = *(const float4*)&be[tid * 4];
    float4 o4;
    o4.x = fmaxf((v.x - mean) * rstd * g4.x + b4.x, 0.f);
    o4.y = fmaxf((v.y - mean) * rstd * g4.y + b4.y, 0.f);
    o4.z = fmaxf((v.z - mean) * rstd * g4.z + b4.z, 0.f);
    o4.w = fmaxf((v.w - mean) * rstd * g4.w + b4.w, 0.f);
    *(float4*)&out[((long)head * B + b) * F + tid * 4] = o4;
}

}  // namespace raff

// =============================================================================
// Launch
// =============================================================================
extern "C" void kernel_launch(void* const* d_in, const int* in_sizes, int n_in,
                              void* d_out, int out_size)
{
    using namespace raff;
    (void)in_sizes; (void)n_in; (void)out_size;

    const float* q         = (const float*)d_in[0];
    const float* in_proj_w = (const float*)d_in[1];
    const float* in_proj_b = (const float*)d_in[2];
    const float* out_w     = (const float*)d_in[3];
    const float* out_b     = (const float*)d_in[4];
    const float* cls_w1    = (const float*)d_in[5];
    const float* cls_b1    = (const float*)d_in[6];
    const float* cls_w2    = (const float*)d_in[7];
    const float* cls_b2    = (const float*)d_in[8];
    const float* fus_w     = (const float*)d_in[9];
    const float* fus_b     = (const float*)d_in[10];
    const float* fus_g     = (const float*)d_in[11];
    const float* fus_be    = (const float*)d_in[12];
    const float* pa_w      = (const float*)d_in[13];
    const float* pa_b      = (const float*)d_in[14];
    const float* pa_g      = (const float*)d_in[15];
    const float* pa_be     = (const float*)d_in[16];
    const float* pv_w      = (const float*)d_in[17];
    const float* pv_b      = (const float*)d_in[18];
    const float* pv_g      = (const float*)d_in[19];
    const float* pv_be     = (const float*)d_in[20];
    float* out = (float*)d_out;

    float *pMC, *pd, *psc, *py, *pvq, *pbcomb, *phb;
    __half *qhi, *w1hi, *uhi, *ulo, *vhi, *vlo,
        *mchi, *mclo, *qvhi, *xhi, *hwhi, *hwlo;
    cudaGetSymbolAddress((void**)&pMC, g_MC);
    cudaGetSymbolAddress((void**)&pd, g_d);
    cudaGetSymbolAddress((void**)&psc, g_scores);
    cudaGetSymbolAddress((void**)&py, g_y);
    cudaGetSymbolAddress((void**)&pvq, g_vq);
    cudaGetSymbolAddress((void**)&pbcomb, g_bcomb);
    cudaGetSymbolAddress((void**)&phb, g_hbias);
    cudaGetSymbolAddress((void**)&qhi, g_q_hi);
    cudaGetSymbolAddress((void**)&w1hi, g_w1_hi);
    cudaGetSymbolAddress((void**)&uhi, g_u_hi);
    cudaGetSymbolAddress((void**)&ulo, g_u_lo);
    cudaGetSymbolAddress((void**)&vhi, g_v_hi);
    cudaGetSymbolAddress((void**)&vlo, g_v_lo);
    cudaGetSymbolAddress((void**)&mchi, g_mc_hi);
    cudaGetSymbolAddress((void**)&mclo, g_mc_lo);
    cudaGetSymbolAddress((void**)&qvhi, g_qv_hi);
    cudaGetSymbolAddress((void**)&xhi, g_x_hi);
    cudaGetSymbolAddress((void**)&hwhi, g_hw_hi);
    cudaGetSymbolAddress((void**)&hwlo, g_hw_lo);

    cudaFuncSetAttribute((const void*)bsgemm<3, false, false, false, false>,
                         cudaFuncAttributeMaxDynamicSharedMemorySize, GEMM_SMEM);
    cudaFuncSetAttribute((const void*)bsgemm<2, true, false, true, false>,
                         cudaFuncAttributeMaxDynamicSharedMemorySize, GEMM_SMEM);
    cudaFuncSetAttribute((const void*)bsgemm<2, true, false, false, false>,
                         cudaFuncAttributeMaxDynamicSharedMemorySize, GEMM_SMEM);
    cudaFuncSetAttribute((const void*)bsgemm<1, true, false, false, true>,
                         cudaFuncAttributeMaxDynamicSharedMemorySize, GEMM_SMEM);
    cudaFuncSetAttribute((const void*)bsgemm<1, false, true, false, false>,
                         cudaFuncAttributeMaxDynamicSharedMemorySize, GEMM_SMEM);
    cudaFuncSetAttribute((const void*)attn_kernel,
                         cudaFuncAttributeMaxDynamicSharedMemorySize, ATTN_SMEM);

    static cudaStream_t s1 = nullptr;
    static cudaEvent_t ef = nullptr, epre = nullptr, ecls = nullptr;
    if (!s1) {
        cudaStreamCreateWithFlags(&s1, cudaStreamNonBlocking);
        cudaEventCreateWithFlags(&ef, cudaEventDisableTiming);
        cudaEventCreateWithFlags(&epre, cudaEventDisableTiming);
        cudaEventCreateWithFlags(&ecls, cudaEventDisableTiming);
    }

    // ---- fork: independent weight conversions on side stream ----
    cudaEventRecord(ef, 0);
    cudaStreamWaitEvent(s1, ef, 0);
    split_hi<<<(int)((long)S * H * D / 4 / 256), 256, 0, s1>>>(
        cls_w1, w1hi, (long)S * H * D / 4);
    split4<<<F * D / 4 / 256, 256, 0, s1>>>(fus_w, hwhi, hwlo, (long)F * D / 4, SWT);
    split4<<<F * D / 4 / 256, 256, 0, s1>>>(pa_w, hwhi + (long)F * D,
                                            hwlo + (long)F * D, (long)F * D / 4, SWT);
    split4<<<F * D / 4 / 256, 256, 0, s1>>>(pv_w, hwhi + 2L * F * D,
                                            hwlo + 2L * F * D, (long)F * D / 4, SWT);

    // ---- main stream: critical path ----
    vec_pre<<<D + 1, 256>>>(in_proj_w, in_proj_b, out_w, out_b);
    misc_init<<<262 + 8192, 256>>>(fus_b, pa_b, pv_b);
    split_hi<<<(int)(NQ / 4 / 256), 256>>>(q, qhi, NQ / 4);
    split4<<<D * D / 4 / 256, 256>>>(out_w, uhi + (long)D * D, ulo + (long)D * D,
                                     D * D / 4, SWT);
    tsplit<<<dim3(32, 32), dim3(32, 8)>>>(in_proj_w + (long)D * D, uhi, ulo);    // WkT
    tsplit<<<dim3(32, 32), dim3(32, 8)>>>(in_proj_w, vhi, vlo);                  // WqT
    tsplit<<<dim3(32, 32), dim3(32, 8)>>>(in_proj_w + 2L * D * D,
                                          vhi + (long)D * D, vlo + (long)D * D); // WvT

    bsgemm<3, false, false, false, false><<<dim3(8, 8, 2), 256, GEMM_SMEM>>>(
        uhi, ulo, D, (long)D * D, vhi, vlo, (long)D * D,
        pMC, D, (long)D * D, nullptr, 0L, nullptr, SC_WW, nullptr);
    split4<<<2 * D * D / 4 / 256, 256>>>(pMC, mchi, mclo, 2 * D * D / 4, SWT);
    cudaEventRecord(epre, 0);

    // ---- concurrent: qM+scores (main) || cls (side) ----
    bsgemm<1, true, false, false, true><<<dim3(8, 512), 256, GEMM_SMEM>>>(
        qhi, nullptr, (long)D, 0L, mchi, nullptr, 0L, psc, 0, 0L,
        pvq, 0L, nullptr, SC_QW, qhi);

    cudaStreamWaitEvent(s1, epre, 0);
    bsgemm<1, false, true, false, false><<<dim3(4, 16, 32), 256, GEMM_SMEM, s1>>>(
        qhi, nullptr, (long)S * D, (long)D, w1hi, nullptr, (long)H * D,
        pd, S, 0L, cls_b1, (long)H, cls_w2, 1.f, nullptr);
    cudaEventRecord(ecls, s1);

    // ---- join: attn needs scores (main) + d (side) ----
    cudaStreamWaitEvent(0, ecls, 0);
    attn_kernel<<<B, 256, ATTN_SMEM>>>(cls_b2, out);

    // [audio; video] = qv * Cov^T + bcomb  (2-term, fp16 out)
    bsgemm<2, true, false, true, false><<<dim3(8, 32), 256, GEMM_SMEM>>>(
        qvhi, nullptr, (long)D, 0L, mchi + (long)D * D, mclo + (long)D * D, 0L,
        (float*)(xhi + (long)B * D), D, 0L, pbcomb, 0L, nullptr, SC_QW, nullptr);

    fuse_half<<<(int)((long)B * D / 8 / 256), 256>>>();

    bsgemm<2, true, false, false, false><<<dim3(4, 16, 3), 256, GEMM_SMEM>>>(
        xhi, nullptr, (long)D, (long)B * D, hwhi, hwlo, (long)F * D,
        py, F, (long)B * F, phb, (long)F, nullptr, SC_QW, nullptr);

    ln_relu<<<dim3(B, 3), 128>>>(fus_g, fus_be, pa_g, pa_be, pv_g, pv_be, out);
}